// round 12
// baseline (speedup 1.0000x reference)
#include <cuda_runtime.h>
#include <cuda_fp16.h>
#include <cstdint>

// ---------------------------------------------------------------------------
// Problem constants
// ---------------------------------------------------------------------------
#define BZ 16
#define SZ 4096
#define DZ 768
#define HH 12
#define HD 64
#define KSZ 9
#define MTOT (BZ*SZ)          // 65536
#define KDIM 768

// Scratch (static device globals; no allocation allowed)
__device__ __align__(256) float g_q[(size_t)BZ*HH*SZ*HD];
__device__ __align__(256) float g_k[(size_t)BZ*HH*SZ*HD];
__device__ __align__(256) float g_v[(size_t)BZ*HH*SZ*HD];
__device__ __align__(256) float g_kv[(size_t)BZ*HH*HD*HD];
__device__ __align__(256) float g_kvp[(size_t)4*BZ*HH*HD*HD];
__device__ __align__(256) __half g_y[(size_t)BZ*SZ*DZ];      // fp16 attn output
__device__ __align__(256) __half g_xc[(size_t)MTOT*KDIM];    // fp16 x
__device__ __align__(256) __half g_wq[(size_t)3*DZ*KDIM];    // fp16 w_qkv
__device__ __align__(256) __half g_wp[(size_t)DZ*KDIM];      // fp16 w_proj

__device__ __forceinline__ float tf32r(float x) {
    uint32_t u;
    asm("cvt.rna.tf32.f32 %0, %1;" : "=r"(u) : "f"(x));
    return __uint_as_float(u);
}

// ---------------------------------------------------------------------------
// Single fused fp16 conversion kernel over x | w_qkv | w_proj (RN, unbiased)
// ---------------------------------------------------------------------------
#define N4_X  (MTOT*KDIM/4)
#define N4_WQ (3*DZ*KDIM/4)
#define N4_WP (DZ*KDIM/4)
__global__ void cvt_all(const float4* __restrict__ x,
                        const float4* __restrict__ wq,
                        const float4* __restrict__ wp)
{
    int i = blockIdx.x * blockDim.x + threadIdx.x;
    const float4* src; __half* dst;
    if (i < N4_X) { src = x + i; dst = g_xc + (size_t)i * 4; }
    else if (i < N4_X + N4_WQ) { i -= N4_X; src = wq + i; dst = g_wq + (size_t)i * 4; }
    else if (i < N4_X + N4_WQ + N4_WP) { i -= N4_X + N4_WQ; src = wp + i; dst = g_wp + (size_t)i * 4; }
    else return;
    float4 v = *src;
    __half2 h01 = __floats2half2_rn(v.x, v.y);
    __half2 h23 = __floats2half2_rn(v.z, v.w);
    uint2 o;
    o.x = *(uint32_t*)&h01;
    o.y = *(uint32_t*)&h23;
    *(uint2*)dst = o;
}

// fp16 mma m16n8k16, fp32 accumulate
__device__ __forceinline__ void mma_f16(float* c, uint32_t a0, uint32_t a1,
                                        uint32_t a2, uint32_t a3,
                                        uint32_t b0, uint32_t b1)
{
    asm volatile("mma.sync.aligned.m16n8k16.row.col.f32.f16.f16.f32 "
                 "{%0,%1,%2,%3}, {%4,%5,%6,%7}, {%8,%9}, {%0,%1,%2,%3};"
                 : "+f"(c[0]), "+f"(c[1]), "+f"(c[2]), "+f"(c[3])
                 : "r"(a0), "r"(a1), "r"(a2), "r"(a3), "r"(b0), "r"(b1));
}

// tf32 mma m16n8k8 (kv + out kernels, unchanged)
__device__ __forceinline__ void mma_tf32(float* c, uint32_t a0, uint32_t a1,
                                         uint32_t a2, uint32_t a3,
                                         uint32_t b0, uint32_t b1)
{
    asm volatile("mma.sync.aligned.m16n8k8.row.col.f32.tf32.tf32.f32 "
                 "{%0,%1,%2,%3}, {%4,%5,%6,%7}, {%8,%9}, {%0,%1,%2,%3};"
                 : "+f"(c[0]), "+f"(c[1]), "+f"(c[2]), "+f"(c[3])
                 : "r"(a0), "r"(a1), "r"(a2), "r"(a3), "r"(b0), "r"(b1));
}

__device__ __forceinline__ void ldsm_x4(uint32_t* r, uint32_t addr)
{
    asm volatile("ldmatrix.sync.aligned.m8n8.x4.shared.b16 {%0,%1,%2,%3}, [%4];"
                 : "=r"(r[0]), "=r"(r[1]), "=r"(r[2]), "=r"(r[3]) : "r"(addr));
}

// ---------------------------------------------------------------------------
// FP16 mma.sync GEMM: C[m,n] = sum_k A[m,k]*W[n,k] + bias[n]
// 128x128x32 CTA tile, 3-stage cp.async ring, 2 CTAs/SM, 8 warps @ 64x32.
// Per chunk: 2 k16-steps, each 4 A-ldsm.x4 + 2 paired B-ldsm.x4 + 16 MMAs.
// SKAh=40 halves/row: 16B-unit index = 5*row mod 8 -> ldmatrix conflict-free,
// and cp.async dst 16B-aligned (80B row pitch).
// ---------------------------------------------------------------------------
#define BMT 128
#define BNT 128
#define BKT 32
#define NSTG 3
#define SKAh 40
#define STG_HALVES (2*BMT*SKAh)          // 10240 halves / stage
#define STG_BYTES  (STG_HALVES*2)        // 20480
#define EPI_STRIDE 132
#define GEMM_SMEM  (BMT*EPI_STRIDE*4)    // 67584 >= 3*STG_BYTES (61440)

__device__ __forceinline__ void stage_load(uint32_t sb, const __half* Abase,
                                           const __half* Bbase, int ko, int tid)
{
#pragma unroll
    for (int j = 0; j < 2; j++) {
        const int idx = tid + j * 256;        // 0..511
        const int row = idx >> 2;             // 0..127
        const int c16 = (idx & 3) * 8;        // half offset within row
        const __half* ga = Abase + (size_t)row * KDIM + ko + c16;
        const __half* gb = Bbase + (size_t)row * KDIM + ko + c16;
        asm volatile("cp.async.cg.shared.global [%0], [%1], 16;"
                     :: "r"(sb + (row * SKAh + c16) * 2), "l"(ga));
        asm volatile("cp.async.cg.shared.global [%0], [%1], 16;"
                     :: "r"(sb + (BMT * SKAh + row * SKAh + c16) * 2), "l"(gb));
    }
    asm volatile("cp.async.commit_group;");
}

template<int MODE, int NCHUNK>
__global__ __launch_bounds__(256, 2)
void gemm_mma(const float* __restrict__ bias, float* __restrict__ Cout)
{
    extern __shared__ __align__(16) float smf[];
    __shared__ float sbias[BNT];

    const int tid  = threadIdx.x;
    const int wid  = tid >> 5;
    const int lane = tid & 31;
    const int l4   = lane >> 2;
    const int lk   = lane & 3;
    const int warpM = wid & 1;
    const int warpN = wid >> 1;

    const int bn = blockIdx.x * BNT;
    const int bm = blockIdx.y * BMT;

    const __half* A = (MODE == 1) ? g_xc : g_y;
    const __half* W = (MODE == 1) ? g_wq : g_wp;
    const __half* Abase = A + (size_t)bm * KDIM;
    const __half* Bbase = W + (size_t)bn * KDIM;

    if (tid < BNT) sbias[tid] = bias[bn + tid];

    uint32_t sm_u32;
    asm("{ .reg .u64 t; cvta.to.shared.u64 t, %1; cvt.u32.u64 %0, t; }"
        : "=r"(sm_u32) : "l"(smf));

    // ldmatrix per-thread addresses (b16 fragments, fp16 m16n8k16)
    // A x4 over 16x16 tile: lanes 0-15 rows m0+l (k 0-7), 16-31 rows m0+(l-16) (k 8-15)
    const int aRow = warpM * 64 + (lane & 15);
    const int aColH = (lane >> 4) * 8;
    const uint32_t aOff = (aRow * SKAh + aColH) * 2;
    // B x4 over PAIR of 8x16 tiles: lanes 0-7 rows n0..7 (k0-7), 8-15 same rows
    // (k8-15), 16-23 rows n8..15 (k0-7), 24-31 (k8-15)
    const int bRow = warpN * 32 + (lane & 7) + ((lane >> 4) & 1) * 8;
    const int bColH = ((lane >> 3) & 1) * 8;
    const uint32_t bOff = (BMT * SKAh + bRow * SKAh + bColH) * 2;

    // prologue: prefetch 2 stages
    stage_load(sm_u32, Abase, Bbase, 0, tid);
    stage_load(sm_u32 + STG_BYTES, Abase, Bbase, BKT, tid);

    float acc[4][4][4];
#pragma unroll
    for (int mi = 0; mi < 4; mi++)
#pragma unroll
        for (int ni = 0; ni < 4; ni++)
#pragma unroll
            for (int r = 0; r < 4; r++) acc[mi][ni][r] = 0.f;

    int st_c = 0;
    for (int c = 0; c < NCHUNK; c++) {
        asm volatile("cp.async.wait_group %0;" :: "n"(1));
        __syncthreads();

        const uint32_t aAddr = sm_u32 + st_c * STG_BYTES + aOff;
        const uint32_t bAddr = sm_u32 + st_c * STG_BYTES + bOff;

#pragma unroll
        for (int kk = 0; kk < 2; kk++) {
            uint32_t af[4][4], bf[2][4];
#pragma unroll
            for (int mi = 0; mi < 4; mi++)
                ldsm_x4(af[mi], aAddr + (mi * 16 * SKAh + kk * 16) * 2);
#pragma unroll
            for (int pp = 0; pp < 2; pp++)
                ldsm_x4(bf[pp], bAddr + (pp * 16 * SKAh + kk * 16) * 2);
#pragma unroll
            for (int mi = 0; mi < 4; mi++)
#pragma unroll
                for (int ni = 0; ni < 4; ni++)
                    mma_f16(acc[mi][ni], af[mi][0], af[mi][1], af[mi][2],
                            af[mi][3], bf[ni >> 1][(ni & 1) * 2],
                            bf[ni >> 1][(ni & 1) * 2 + 1]);
        }

        // prefetch chunk c+2 (R11 position: after the MMA block)
        const int stp = st_c ? st_c - 1 : 2;
        if (c + 2 < NCHUNK)
            stage_load(sm_u32 + stp * STG_BYTES, Abase, Bbase, (c + 2) * BKT, tid);
        else
            asm volatile("cp.async.commit_group;");
        st_c = (st_c == 2) ? 0 : st_c + 1;
    }

    // ---- epilogue (fp32) ----
    asm volatile("cp.async.wait_group %0;" :: "n"(0));
    __syncthreads();
    float* st = smf;
#pragma unroll
    for (int mi = 0; mi < 4; mi++)
#pragma unroll
        for (int ni = 0; ni < 4; ni++) {
            const int r = warpM * 64 + mi * 16 + l4;
            const int cc = warpN * 32 + ni * 8 + lk * 2;
            st[r * EPI_STRIDE + cc]           = acc[mi][ni][0];
            st[r * EPI_STRIDE + cc + 1]       = acc[mi][ni][1];
            st[(r + 8) * EPI_STRIDE + cc]     = acc[mi][ni][2];
            st[(r + 8) * EPI_STRIDE + cc + 1] = acc[mi][ni][3];
        }
    __syncthreads();

    if (MODE == 0) {
#pragma unroll 1
        for (int i = 0; i < 16; i++) {
            const int r = wid * 16 + i;
            float4 u = *(const float4*)(st + (size_t)r * EPI_STRIDE + lane * 4);
            u.x += sbias[lane * 4];     u.y += sbias[lane * 4 + 1];
            u.z += sbias[lane * 4 + 2]; u.w += sbias[lane * 4 + 3];
            *(float4*)(Cout + (size_t)(bm + r) * DZ + bn + lane * 4) = u;
        }
    } else {
        const int part = bn / DZ;
        const int col0 = bn - part * DZ;
        const int h0 = col0 >> 6;
        float* dbuf = (part == 0) ? g_q : (part == 1) ? g_k : g_v;
#pragma unroll 1
        for (int i = 0; i < 16; i++) {
            const int r = wid * 16 + i;
            const int m = bm + r;
            const int b = m >> 12;
            const int s = m & (SZ - 1);
            float2 u0 = *(const float2*)(st + (size_t)r * EPI_STRIDE + lane * 2);
            float2 u1 = *(const float2*)(st + (size_t)r * EPI_STRIDE + 64 + lane * 2);
            u0.x += sbias[lane * 2];      u0.y += sbias[lane * 2 + 1];
            u1.x += sbias[64 + lane * 2]; u1.y += sbias[64 + lane * 2 + 1];
            if (part < 2) {
                float ss0 = u0.x * u0.x + u0.y * u0.y;
                float ss1 = u1.x * u1.x + u1.y * u1.y;
#pragma unroll
                for (int o = 16; o; o >>= 1) {
                    ss0 += __shfl_xor_sync(0xffffffffu, ss0, o);
                    ss1 += __shfl_xor_sync(0xffffffffu, ss1, o);
                }
                const float r0 = rsqrtf(ss0), r1 = rsqrtf(ss1);
                u0.x *= r0; u0.y *= r0;
                u1.x *= r1; u1.y *= r1;
            }
            const size_t base0 = ((((size_t)b * HH + h0) * SZ + s) << 6) + lane * 2;
            const size_t base1 = ((((size_t)b * HH + h0 + 1) * SZ + s) << 6) + lane * 2;
            *(float2*)(dbuf + base0) = u0;
            *(float2*)(dbuf + base1) = u1;
        }
    }
}

// ---------------------------------------------------------------------------
// kv partials: kvp[part][bh] = sum_{s in part} k^T v over 1024 seq positions.
// grid (4, 192); deterministic (no atomics). Swizzled [d][s] smem layout.
// ---------------------------------------------------------------------------
__global__ __launch_bounds__(256) void kv_mma()
{
    __shared__ float ks[64 * 32];
    __shared__ float vs[64 * 32];

    const int part = blockIdx.x;
    const int bh = blockIdx.y;
    const float* Kb = g_k + (size_t)bh * SZ * HD;
    const float* Vb = g_v + (size_t)bh * SZ * HD;

    const int tid = threadIdx.x;
    const int wid = tid >> 5, lane = tid & 31;
    const int l4 = lane >> 2, lk = lane & 3;
    const int wm = wid & 1, wn = wid >> 1;

    const int dL = tid & 63;
    const int sg = tid >> 6;
    const int swzL = ((dL & 7) << 2) + (dL >> 3);
    const int sbase = dL * 32;

    const int d0 = wm * 32 + l4;
    const int e0 = wn * 16 + l4;

    float acc[2][2][4];
#pragma unroll
    for (int mi = 0; mi < 2; mi++)
#pragma unroll
        for (int ni = 0; ni < 2; ni++)
#pragma unroll
            for (int r = 0; r < 4; r++) acc[mi][ni][r] = 0.f;

    const int s_lo = part * 1024;
    for (int s0 = s_lo; s0 < s_lo + 1024; s0 += 32) {
        float kr[8], vr[8];
#pragma unroll
        for (int i = 0; i < 8; i++) {
            const int s = s0 + sg + i * 4;
            kr[i] = Kb[(size_t)s * 64 + dL];
            vr[i] = Vb[(size_t)s * 64 + dL];
        }
        __syncthreads();
#pragma unroll
        for (int i = 0; i < 8; i++) {
            const int col = (sg + i * 4 + swzL) & 31;
            ks[sbase + col] = tf32r(kr[i]);
            vs[sbase + col] = tf32r(vr[i]);
        }
        __syncthreads();

#pragma unroll
        for (int kk = 0; kk < 4; kk++) {
            const int c0 = kk * 8 + lk;
            uint32_t af[2][4], bf[2][2];
#pragma unroll
            for (int mi = 0; mi < 2; mi++) {
                const int da = d0 + mi * 16;
                const int db = da + 8;
                const int swa = ((da & 7) << 2) + (da >> 3);
                const int swb = swa + 1;
                af[mi][0] = __float_as_uint(ks[da * 32 + ((c0 + swa) & 31)]);
                af[mi][1] = __float_as_uint(ks[db * 32 + ((c0 + swb) & 31)]);
                af[mi][2] = __float_as_uint(ks[da * 32 + ((c0 + 4 + swa) & 31)]);
                af[mi][3] = __float_as_uint(ks[db * 32 + ((c0 + 4 + swb) & 31)]);
            }
#pragma unroll
            for (int ni = 0; ni < 2; ni++) {
                const int ea = e0 + ni * 8;
                const int swe = ((ea & 7) << 2) + (ea >> 3);
                bf[ni][0] = __float_as_uint(vs[ea * 32 + ((c0 + swe) & 31)]);
                bf[ni][1] = __float_as_uint(vs[ea * 32 + ((c0 + 4 + swe) & 31)]);
            }
#pragma unroll
            for (int mi = 0; mi < 2; mi++)
#pragma unroll
                for (int ni = 0; ni < 2; ni++)
                    mma_tf32(acc[mi][ni], af[mi][0], af[mi][1], af[mi][2],
                             af[mi][3], bf[ni][0], bf[ni][1]);
        }
    }

    float* out = g_kvp + ((size_t)part * BZ * HH + bh) * HD * HD;
#pragma unroll
    for (int mi = 0; mi < 2; mi++)
#pragma unroll
        for (int ni = 0; ni < 2; ni++) {
            const int d = wm * 32 + mi * 16 + l4;
            const int e = wn * 16 + ni * 8 + lk * 2;
            *(float2*)&out[d * 64 + e]       = make_float2(acc[mi][ni][0], acc[mi][ni][1]);
            *(float2*)&out[(d + 8) * 64 + e] = make_float2(acc[mi][ni][2], acc[mi][ni][3]);
        }
}

// Sum the 4 kv partials into g_kv.
__global__ void kv_reduce()
{
    const size_t i = ((size_t)blockIdx.x * blockDim.x + threadIdx.x) * 4;
    const size_t stride = (size_t)BZ * HH * HD * HD;
    float4 a = *(const float4*)&g_kvp[i];
    float4 b = *(const float4*)&g_kvp[i + stride];
    float4 c = *(const float4*)&g_kvp[i + 2 * stride];
    float4 d = *(const float4*)&g_kvp[i + 3 * stride];
    a.x += b.x + c.x + d.x;  a.y += b.y + c.y + d.y;
    a.z += b.z + c.z + d.z;  a.w += b.w + c.w + d.w;
    *(float4*)&g_kv[i] = a;
}

// ---------------------------------------------------------------------------
// out = normalize(0.5*v + (1/pi) q@kv) + dconv(v); q@kv via tf32 mma.sync.
// smem: kvT[64][68] (kv transposed) | qs[64][68] (aliased ob) | vext[72][64]
// Output written to g_y as fp16 (proj GEMM input).
// ---------------------------------------------------------------------------
#define OS_KVT 0
#define OS_QS  (64*68)
#define OS_VX  (2*64*68)
#define OS_WD  (2*64*68 + 72*64)
#define OUT_SMEM_FLOATS (2*64*68 + 72*64 + 16)
#define OUT_SMEM_BYTES  (OUT_SMEM_FLOATS * 4)

__global__ __launch_bounds__(256) void out_kernel(const float* __restrict__ wd)
{
    extern __shared__ float sm[];
    float* kvT  = sm + OS_KVT;
    float* qs   = sm + OS_QS;
    float* ob   = qs;
    float (*vext)[64] = (float(*)[64])(sm + OS_VX);
    float* wds  = sm + OS_WD;

    const int bh = blockIdx.y;
    const int bb = bh / HH;
    const int h  = bh % HH;
    const int s0 = blockIdx.x * 64;

    const float* Qb = g_q + (size_t)bh * SZ * HD;
    const float* Vb = g_v + (size_t)bh * SZ * HD;
    const float* KVb = g_kv + (size_t)bh * HD * HD;

    const int tid = threadIdx.x;
    const int wid = tid >> 5, lane = tid & 31;
    const int l4 = lane >> 2, lk = lane & 3;
    const int wm = wid & 1, wn = wid >> 1;

#pragma unroll
    for (int i = tid * 4; i < 4096; i += 1024) {
        const int d = i >> 6, e = i & 63;
        float4 kvv = *(const float4*)(KVb + i);
        kvT[(e + 0) * 68 + d] = tf32r(kvv.x);
        kvT[(e + 1) * 68 + d] = tf32r(kvv.y);
        kvT[(e + 2) * 68 + d] = tf32r(kvv.z);
        kvT[(e + 3) * 68 + d] = tf32r(kvv.w);
    }

#pragma unroll
    for (int i = tid * 4; i < 4096; i += 1024) {
        const int r = i >> 6, c = i & 63;
        float4 qv = *(const float4*)(Qb + (size_t)(s0 + r) * 64 + c);
        qv.x = tf32r(qv.x); qv.y = tf32r(qv.y);
        qv.z = tf32r(qv.z); qv.w = tf32r(qv.w);
        *(float4*)(qs + r * 68 + c) = qv;
    }

    for (int i = tid * 4; i < 72 * 64; i += 1024) {
        const int r = i >> 6, c = i & 63;
        const int gs = s0 - 4 + r;
        float4 val = make_float4(0.f, 0.f, 0.f, 0.f);
        if (gs >= 0 && gs < SZ)
            val = *(const float4*)(Vb + (size_t)gs * 64 + c);
        *(float4*)&vext[r][c] = val;
    }
    if (tid < KSZ) wds[tid] = wd[h * KSZ + tid];
    __syncthreads();

    float acc[2][2][4];
#pragma unroll
    for (int mi = 0; mi < 2; mi++)
#pragma unroll
        for (int ni = 0; ni < 2; ni++)
#pragma unroll
            for (int r = 0; r < 4; r++) acc[mi][ni][r] = 0.f;

#pragma unroll
    for (int kk = 0; kk < 8; kk++) {
        const int d = kk * 8 + lk;
        uint32_t af[2][4], bf[2][2];
#pragma unroll
        for (int mi = 0; mi < 2; mi++) {
            const int m0 = wm * 32 + mi * 16 + l4;
            af[mi][0] = __float_as_uint(qs[m0 * 68 + d]);
            af[mi][1] = __float_as_uint(qs[(m0 + 8) * 68 + d]);
            af[mi][2] = __float_as_uint(qs[m0 * 68 + d + 4]);
            af[mi][3] = __float_as_uint(qs[(m0 + 8) * 68 + d + 4]);
        }
#pragma unroll
        for (int ni = 0; ni < 2; ni++) {
            const int n0 = wn * 16 + ni * 8 + l4;
            bf[ni][0] = __float_as_uint(kvT[n0 * 68 + d]);
            bf[ni][1] = __float_as_uint(kvT[n0 * 68 + d + 4]);
        }
#pragma unroll
        for (int mi = 0; mi < 2; mi++)
#pragma unroll
            for (int ni = 0; ni < 2; ni++)
                mma_tf32(acc[mi][ni], af[mi][0], af[mi][1], af[mi][2],
                         af[mi][3], bf[ni][0], bf[ni][1]);
    }
    __syncthreads();

#pragma unroll
    for (int mi = 0; mi < 2; mi++)
#pragma unroll
        for (int ni = 0; ni < 2; ni++) {
            const int r = wm * 32 + mi * 16 + l4;
            const int cc = wn * 16 + ni * 8 + lk * 2;
            ob[r * 68 + cc]           = acc[mi][ni][0];
            ob[r * 68 + cc + 1]       = acc[mi][ni][1];
            ob[(r + 8) * 68 + cc]     = acc[mi][ni][2];
            ob[(r + 8) * 68 + cc + 1] = acc[mi][ni][3];
        }
    __syncthreads();

    const float INV_PI = 0.3183098861837907f;
#pragma unroll
    for (int k = 0; k < 8; k++) {
        const int rr = wid * 8 + k;
        const float v0 = 0.5f * vext[rr + 4][lane]      + INV_PI * ob[rr * 68 + lane];
        const float v1 = 0.5f * vext[rr + 4][lane + 32] + INV_PI * ob[rr * 68 + lane + 32];
        float ss = v0 * v0 + v1 * v1;
#pragma unroll
        for (int o = 16; o; o >>= 1) ss += __shfl_xor_sync(0xffffffffu, ss, o);
        const float rn = rsqrtf(ss);
        float c0 = 0.f, c1 = 0.f;
#pragma unroll
        for (int j = 0; j < KSZ; j++) {
            const float w = wds[j];
            c0 += vext[rr + j][lane] * w;
            c1 += vext[rr + j][lane + 32] * w;
        }
        const int sg = s0 + rr;
        __half* dst = g_y + ((size_t)bb * SZ + sg) * DZ + h * HD;
        dst[lane]      = __float2half_rn(v0 * rn + c0);
        dst[lane + 32] = __float2half_rn(v1 * rn + c1);
    }
}

// ---------------------------------------------------------------------------
extern "C" void kernel_launch(void* const* d_in, const int* in_sizes, int n_in,
                              void* d_out, int out_size)
{
    const float* x      = (const float*)d_in[0];
    const float* w_qkv  = (const float*)d_in[1];
    const float* b_qkv  = (const float*)d_in[2];
    const float* w_proj = (const float*)d_in[3];
    const float* b_proj = (const float*)d_in[4];
    const float* w_dcv  = (const float*)d_in[5];
    float* out = (float*)d_out;

    cudaFuncSetAttribute(gemm_mma<1, KDIM/BKT>, cudaFuncAttributeMaxDynamicSharedMemorySize, GEMM_SMEM);
    cudaFuncSetAttribute(gemm_mma<0, KDIM/BKT>, cudaFuncAttributeMaxDynamicSharedMemorySize, GEMM_SMEM);
    cudaFuncSetAttribute(out_kernel, cudaFuncAttributeMaxDynamicSharedMemorySize, OUT_SMEM_BYTES);

    // fp16-convert all GEMM inputs in one launch (RN, unbiased)
    const int n4_total = N4_X + N4_WQ + N4_WP;
    cvt_all<<<(n4_total + 255) / 256, 256>>>((const float4*)x,
                                             (const float4*)w_qkv,
                                             (const float4*)w_proj);

    // QKV projection (fp16 mma) + fused bias + q/k normalize + scatter
    gemm_mma<1, KDIM/BKT><<<dim3(3 * DZ / BNT, MTOT / BMT), 256, GEMM_SMEM>>>(b_qkv, nullptr);
    // kv = k^T v: 4 deterministic S-partials + reduce (tf32)
    kv_mma<<<dim3(4, BZ * HH), 256>>>();
    kv_reduce<<<(BZ * HH * HD * HD) / 1024, 256>>>();
    // angular attention core (tf32) + norm + dconv + relayout -> fp16 g_y
    out_kernel<<<dim3(SZ / 64, BZ * HH), 256, OUT_SMEM_BYTES>>>(w_dcv);
    // output projection (fp16 mma)
    gemm_mma<0, KDIM/BKT><<<dim3(DZ / BNT, MTOT / BMT), 256, GEMM_SMEM>>>(b_proj, out);
}

// round 14
// speedup vs baseline: 1.1133x; 1.1133x over previous
#include <cuda_runtime.h>
#include <cuda_fp16.h>
#include <cstdint>

// ---------------------------------------------------------------------------
// Problem constants
// ---------------------------------------------------------------------------
#define BZ 16
#define SZ 4096
#define DZ 768
#define HH 12
#define HD 64
#define KSZ 9
#define MTOT (BZ*SZ)          // 65536
#define KDIM 768

// Scratch (static device globals; no allocation allowed)
__device__ __align__(256) float g_q[(size_t)BZ*HH*SZ*HD];
__device__ __align__(256) float g_k[(size_t)BZ*HH*SZ*HD];
__device__ __align__(256) float g_v[(size_t)BZ*HH*SZ*HD];
__device__ __align__(256) float g_kv[(size_t)BZ*HH*HD*HD];
__device__ __align__(256) float g_kvp[(size_t)4*BZ*HH*HD*HD];
__device__ __align__(256) __half g_y[(size_t)BZ*SZ*DZ];      // fp16 attn output
__device__ __align__(256) __half g_xc[(size_t)MTOT*KDIM];    // fp16 x
__device__ __align__(256) __half g_wq[(size_t)3*DZ*KDIM];    // fp16 w_qkv
__device__ __align__(256) __half g_wp[(size_t)DZ*KDIM];      // fp16 w_proj

__device__ __forceinline__ float tf32r(float x) {
    uint32_t u;
    asm("cvt.rna.tf32.f32 %0, %1;" : "=r"(u) : "f"(x));
    return __uint_as_float(u);
}

// ---------------------------------------------------------------------------
// Single fused fp16 conversion kernel over x | w_qkv | w_proj (RN, unbiased)
// ---------------------------------------------------------------------------
#define N4_X  (MTOT*KDIM/4)
#define N4_WQ (3*DZ*KDIM/4)
#define N4_WP (DZ*KDIM/4)
__global__ void cvt_all(const float4* __restrict__ x,
                        const float4* __restrict__ wq,
                        const float4* __restrict__ wp)
{
    int i = blockIdx.x * blockDim.x + threadIdx.x;
    const float4* src; __half* dst;
    if (i < N4_X) { src = x + i; dst = g_xc + (size_t)i * 4; }
    else if (i < N4_X + N4_WQ) { i -= N4_X; src = wq + i; dst = g_wq + (size_t)i * 4; }
    else if (i < N4_X + N4_WQ + N4_WP) { i -= N4_X + N4_WQ; src = wp + i; dst = g_wp + (size_t)i * 4; }
    else return;
    float4 v = *src;
    __half2 h01 = __floats2half2_rn(v.x, v.y);
    __half2 h23 = __floats2half2_rn(v.z, v.w);
    uint2 o;
    o.x = *(uint32_t*)&h01;
    o.y = *(uint32_t*)&h23;
    *(uint2*)dst = o;
}

// fp16 mma m16n8k16, fp32 accumulate
__device__ __forceinline__ void mma_f16(float* c, uint32_t a0, uint32_t a1,
                                        uint32_t a2, uint32_t a3,
                                        uint32_t b0, uint32_t b1)
{
    asm volatile("mma.sync.aligned.m16n8k16.row.col.f32.f16.f16.f32 "
                 "{%0,%1,%2,%3}, {%4,%5,%6,%7}, {%8,%9}, {%0,%1,%2,%3};"
                 : "+f"(c[0]), "+f"(c[1]), "+f"(c[2]), "+f"(c[3])
                 : "r"(a0), "r"(a1), "r"(a2), "r"(a3), "r"(b0), "r"(b1));
}

// tf32 mma m16n8k8 (kv + out kernels)
__device__ __forceinline__ void mma_tf32(float* c, uint32_t a0, uint32_t a1,
                                         uint32_t a2, uint32_t a3,
                                         uint32_t b0, uint32_t b1)
{
    asm volatile("mma.sync.aligned.m16n8k8.row.col.f32.tf32.tf32.f32 "
                 "{%0,%1,%2,%3}, {%4,%5,%6,%7}, {%8,%9}, {%0,%1,%2,%3};"
                 : "+f"(c[0]), "+f"(c[1]), "+f"(c[2]), "+f"(c[3])
                 : "r"(a0), "r"(a1), "r"(a2), "r"(a3), "r"(b0), "r"(b1));
}

__device__ __forceinline__ void ldsm_x4(uint32_t* r, uint32_t addr)
{
    asm volatile("ldmatrix.sync.aligned.m8n8.x4.shared.b16 {%0,%1,%2,%3}, [%4];"
                 : "=r"(r[0]), "=r"(r[1]), "=r"(r[2]), "=r"(r[3]) : "r"(addr));
}

// ---------------------------------------------------------------------------
// FP16 mma.sync GEMM: C[m,n] = sum_k A[m,k]*W[n,k] + bias[n]
// 128x128x64 CTA tile (BKT=64 -> 12 chunks, HALF the barriers of R11),
// 3-stage cp.async ring, 2 CTAs/SM, 8 warps @ 64x32.
// Per chunk: 4 k16-steps x (4 A-ldsm.x4 + 2 paired B-ldsm.x4 + 16 MMAs)
//          = 64 MMAs/chunk/warp (same per-barrier work as the R11 winner).
// SKAh=72 halves/row: 16B-unit index = 9*row = row mod 8 -> ldmatrix
// conflict-free; cp.async dsts 16B-aligned (144B row pitch).
// ---------------------------------------------------------------------------
#define BMT 128
#define BNT 128
#define BKT 64
#define NSTG 3
#define SKAh 72
#define STG_HALVES (2*BMT*SKAh)          // 18432 halves / stage
#define STG_BYTES  (STG_HALVES*2)        // 36864
#define GEMM_SMEM  (NSTG*STG_BYTES)      // 110592 (>= epilogue 67584)
#define EPI_STRIDE 132

__device__ __forceinline__ void stage_load(uint32_t sb, const __half* Abase,
                                           const __half* Bbase, int ko, int tid)
{
#pragma unroll
    for (int j = 0; j < 4; j++) {
        const int idx = tid + j * 256;        // 0..1023
        const int row = idx >> 3;             // 0..127
        const int c16 = (idx & 7) * 8;        // half offset within row (0..56)
        const __half* ga = Abase + (size_t)row * KDIM + ko + c16;
        const __half* gb = Bbase + (size_t)row * KDIM + ko + c16;
        asm volatile("cp.async.cg.shared.global [%0], [%1], 16;"
                     :: "r"(sb + (row * SKAh + c16) * 2), "l"(ga));
        asm volatile("cp.async.cg.shared.global [%0], [%1], 16;"
                     :: "r"(sb + (BMT * SKAh + row * SKAh + c16) * 2), "l"(gb));
    }
    asm volatile("cp.async.commit_group;");
}

template<int MODE, int NCHUNK>
__global__ __launch_bounds__(256, 2)
void gemm_mma(const float* __restrict__ bias, float* __restrict__ Cout)
{
    extern __shared__ __align__(16) float smf[];
    __shared__ float sbias[BNT];

    const int tid  = threadIdx.x;
    const int wid  = tid >> 5;
    const int lane = tid & 31;
    const int l4   = lane >> 2;
    const int lk   = lane & 3;
    const int warpM = wid & 1;
    const int warpN = wid >> 1;

    const int bn = blockIdx.x * BNT;
    const int bm = blockIdx.y * BMT;

    const __half* A = (MODE == 1) ? g_xc : g_y;
    const __half* W = (MODE == 1) ? g_wq : g_wp;
    const __half* Abase = A + (size_t)bm * KDIM;
    const __half* Bbase = W + (size_t)bn * KDIM;

    if (tid < BNT) sbias[tid] = bias[bn + tid];

    uint32_t sm_u32;
    asm("{ .reg .u64 t; cvta.to.shared.u64 t, %1; cvt.u32.u64 %0, t; }"
        : "=r"(sm_u32) : "l"(smf));

    // ldmatrix per-thread addresses (b16 fragments, fp16 m16n8k16)
    // A x4 over 16x16 tile: lanes 0-15 rows m0+l (k 0-7), 16-31 same rows (k 8-15)
    const int aRow = warpM * 64 + (lane & 15);
    const int aColH = (lane >> 4) * 8;
    const uint32_t aOff = (aRow * SKAh + aColH) * 2;
    // B x4 over PAIR of 8x16 tiles: lanes 0-7 rows n0..7 (k0-7), 8-15 same rows
    // (k8-15), 16-23 rows n8..15 (k0-7), 24-31 (k8-15)
    const int bRow = warpN * 32 + (lane & 7) + ((lane >> 4) & 1) * 8;
    const int bColH = ((lane >> 3) & 1) * 8;
    const uint32_t bOff = (BMT * SKAh + bRow * SKAh + bColH) * 2;

    // prologue: prefetch 2 stages
    stage_load(sm_u32, Abase, Bbase, 0, tid);
    stage_load(sm_u32 + STG_BYTES, Abase, Bbase, BKT, tid);

    float acc[4][4][4];
#pragma unroll
    for (int mi = 0; mi < 4; mi++)
#pragma unroll
        for (int ni = 0; ni < 4; ni++)
#pragma unroll
            for (int r = 0; r < 4; r++) acc[mi][ni][r] = 0.f;

    int st_c = 0;
    for (int c = 0; c < NCHUNK; c++) {
        asm volatile("cp.async.wait_group %0;" :: "n"(1));
        __syncthreads();

        const uint32_t aAddr = sm_u32 + st_c * STG_BYTES + aOff;
        const uint32_t bAddr = sm_u32 + st_c * STG_BYTES + bOff;

#pragma unroll
        for (int kk = 0; kk < 4; kk++) {
            uint32_t af[4][4], bf[2][4];
#pragma unroll
            for (int mi = 0; mi < 4; mi++)
                ldsm_x4(af[mi], aAddr + (mi * 16 * SKAh + kk * 16) * 2);
#pragma unroll
            for (int pp = 0; pp < 2; pp++)
                ldsm_x4(bf[pp], bAddr + (pp * 16 * SKAh + kk * 16) * 2);
#pragma unroll
            for (int mi = 0; mi < 4; mi++)
#pragma unroll
                for (int ni = 0; ni < 4; ni++)
                    mma_f16(acc[mi][ni], af[mi][0], af[mi][1], af[mi][2],
                            af[mi][3], bf[ni >> 1][(ni & 1) * 2],
                            bf[ni >> 1][(ni & 1) * 2 + 1]);
        }

        // prefetch chunk c+2 (after the MMA block — R11-proven position)
        const int stp = st_c ? st_c - 1 : 2;
        if (c + 2 < NCHUNK)
            stage_load(sm_u32 + stp * STG_BYTES, Abase, Bbase, (c + 2) * BKT, tid);
        else
            asm volatile("cp.async.commit_group;");
        st_c = (st_c == 2) ? 0 : st_c + 1;
    }

    // ---- epilogue (fp32) ----
    asm volatile("cp.async.wait_group %0;" :: "n"(0));
    __syncthreads();
    float* st = smf;
#pragma unroll
    for (int mi = 0; mi < 4; mi++)
#pragma unroll
        for (int ni = 0; ni < 4; ni++) {
            const int r = warpM * 64 + mi * 16 + l4;
            const int cc = warpN * 32 + ni * 8 + lk * 2;
            st[r * EPI_STRIDE + cc]           = acc[mi][ni][0];
            st[r * EPI_STRIDE + cc + 1]       = acc[mi][ni][1];
            st[(r + 8) * EPI_STRIDE + cc]     = acc[mi][ni][2];
            st[(r + 8) * EPI_STRIDE + cc + 1] = acc[mi][ni][3];
        }
    __syncthreads();

    if (MODE == 0) {
#pragma unroll 1
        for (int i = 0; i < 16; i++) {
            const int r = wid * 16 + i;
            float4 u = *(const float4*)(st + (size_t)r * EPI_STRIDE + lane * 4);
            u.x += sbias[lane * 4];     u.y += sbias[lane * 4 + 1];
            u.z += sbias[lane * 4 + 2]; u.w += sbias[lane * 4 + 3];
            *(float4*)(Cout + (size_t)(bm + r) * DZ + bn + lane * 4) = u;
        }
    } else {
        const int part = bn / DZ;
        const int col0 = bn - part * DZ;
        const int h0 = col0 >> 6;
        float* dbuf = (part == 0) ? g_q : (part == 1) ? g_k : g_v;
#pragma unroll 1
        for (int i = 0; i < 16; i++) {
            const int r = wid * 16 + i;
            const int m = bm + r;
            const int b = m >> 12;
            const int s = m & (SZ - 1);
            float2 u0 = *(const float2*)(st + (size_t)r * EPI_STRIDE + lane * 2);
            float2 u1 = *(const float2*)(st + (size_t)r * EPI_STRIDE + 64 + lane * 2);
            u0.x += sbias[lane * 2];      u0.y += sbias[lane * 2 + 1];
            u1.x += sbias[64 + lane * 2]; u1.y += sbias[64 + lane * 2 + 1];
            if (part < 2) {
                float ss0 = u0.x * u0.x + u0.y * u0.y;
                float ss1 = u1.x * u1.x + u1.y * u1.y;
#pragma unroll
                for (int o = 16; o; o >>= 1) {
                    ss0 += __shfl_xor_sync(0xffffffffu, ss0, o);
                    ss1 += __shfl_xor_sync(0xffffffffu, ss1, o);
                }
                const float r0 = rsqrtf(ss0), r1 = rsqrtf(ss1);
                u0.x *= r0; u0.y *= r0;
                u1.x *= r1; u1.y *= r1;
            }
            const size_t base0 = ((((size_t)b * HH + h0) * SZ + s) << 6) + lane * 2;
            const size_t base1 = ((((size_t)b * HH + h0 + 1) * SZ + s) << 6) + lane * 2;
            *(float2*)(dbuf + base0) = u0;
            *(float2*)(dbuf + base1) = u1;
        }
    }
}

// ---------------------------------------------------------------------------
// kv partials: kvp[part][bh] = sum_{s in part} k^T v over 1024 seq positions.
// grid (4, 192); deterministic (no atomics). Swizzled [d][s] smem layout.
// ---------------------------------------------------------------------------
__global__ __launch_bounds__(256) void kv_mma()
{
    __shared__ float ks[64 * 32];
    __shared__ float vs[64 * 32];

    const int part = blockIdx.x;
    const int bh = blockIdx.y;
    const float* Kb = g_k + (size_t)bh * SZ * HD;
    const float* Vb = g_v + (size_t)bh * SZ * HD;

    const int tid = threadIdx.x;
    const int wid = tid >> 5, lane = tid & 31;
    const int l4 = lane >> 2, lk = lane & 3;
    const int wm = wid & 1, wn = wid >> 1;

    const int dL = tid & 63;
    const int sg = tid >> 6;
    const int swzL = ((dL & 7) << 2) + (dL >> 3);
    const int sbase = dL * 32;

    const int d0 = wm * 32 + l4;
    const int e0 = wn * 16 + l4;

    float acc[2][2][4];
#pragma unroll
    for (int mi = 0; mi < 2; mi++)
#pragma unroll
        for (int ni = 0; ni < 2; ni++)
#pragma unroll
            for (int r = 0; r < 4; r++) acc[mi][ni][r] = 0.f;

    const int s_lo = part * 1024;
    for (int s0 = s_lo; s0 < s_lo + 1024; s0 += 32) {
        float kr[8], vr[8];
#pragma unroll
        for (int i = 0; i < 8; i++) {
            const int s = s0 + sg + i * 4;
            kr[i] = Kb[(size_t)s * 64 + dL];
            vr[i] = Vb[(size_t)s * 64 + dL];
        }
        __syncthreads();
#pragma unroll
        for (int i = 0; i < 8; i++) {
            const int col = (sg + i * 4 + swzL) & 31;
            ks[sbase + col] = tf32r(kr[i]);
            vs[sbase + col] = tf32r(vr[i]);
        }
        __syncthreads();

#pragma unroll
        for (int kk = 0; kk < 4; kk++) {
            const int c0 = kk * 8 + lk;
            uint32_t af[2][4], bf[2][2];
#pragma unroll
            for (int mi = 0; mi < 2; mi++) {
                const int da = d0 + mi * 16;
                const int db = da + 8;
                const int swa = ((da & 7) << 2) + (da >> 3);
                const int swb = swa + 1;
                af[mi][0] = __float_as_uint(ks[da * 32 + ((c0 + swa) & 31)]);
                af[mi][1] = __float_as_uint(ks[db * 32 + ((c0 + swb) & 31)]);
                af[mi][2] = __float_as_uint(ks[da * 32 + ((c0 + 4 + swa) & 31)]);
                af[mi][3] = __float_as_uint(ks[db * 32 + ((c0 + 4 + swb) & 31)]);
            }
#pragma unroll
            for (int ni = 0; ni < 2; ni++) {
                const int ea = e0 + ni * 8;
                const int swe = ((ea & 7) << 2) + (ea >> 3);
                bf[ni][0] = __float_as_uint(vs[ea * 32 + ((c0 + swe) & 31)]);
                bf[ni][1] = __float_as_uint(vs[ea * 32 + ((c0 + 4 + swe) & 31)]);
            }
#pragma unroll
            for (int mi = 0; mi < 2; mi++)
#pragma unroll
                for (int ni = 0; ni < 2; ni++)
                    mma_tf32(acc[mi][ni], af[mi][0], af[mi][1], af[mi][2],
                             af[mi][3], bf[ni][0], bf[ni][1]);
        }
    }

    float* out = g_kvp + ((size_t)part * BZ * HH + bh) * HD * HD;
#pragma unroll
    for (int mi = 0; mi < 2; mi++)
#pragma unroll
        for (int ni = 0; ni < 2; ni++) {
            const int d = wm * 32 + mi * 16 + l4;
            const int e = wn * 16 + ni * 8 + lk * 2;
            *(float2*)&out[d * 64 + e]       = make_float2(acc[mi][ni][0], acc[mi][ni][1]);
            *(float2*)&out[(d + 8) * 64 + e] = make_float2(acc[mi][ni][2], acc[mi][ni][3]);
        }
}

// Sum the 4 kv partials into g_kv.
__global__ void kv_reduce()
{
    const size_t i = ((size_t)blockIdx.x * blockDim.x + threadIdx.x) * 4;
    const size_t stride = (size_t)BZ * HH * HD * HD;
    float4 a = *(const float4*)&g_kvp[i];
    float4 b = *(const float4*)&g_kvp[i + stride];
    float4 c = *(const float4*)&g_kvp[i + 2 * stride];
    float4 d = *(const float4*)&g_kvp[i + 3 * stride];
    a.x += b.x + c.x + d.x;  a.y += b.y + c.y + d.y;
    a.z += b.z + c.z + d.z;  a.w += b.w + c.w + d.w;
    *(float4*)&g_kv[i] = a;
}

// ---------------------------------------------------------------------------
// out = normalize(0.5*v + (1/pi) q@kv) + dconv(v); q@kv via tf32 mma.sync.
// smem: kvT[64][68] | qs[64][68] (aliased ob) | vext[72][64]; g_y stored fp16.
// ---------------------------------------------------------------------------
#define OS_KVT 0
#define OS_QS  (64*68)
#define OS_VX  (2*64*68)
#define OS_WD  (2*64*68 + 72*64)
#define OUT_SMEM_FLOATS (2*64*68 + 72*64 + 16)
#define OUT_SMEM_BYTES  (OUT_SMEM_FLOATS * 4)

__global__ __launch_bounds__(256) void out_kernel(const float* __restrict__ wd)
{
    extern __shared__ float sm[];
    float* kvT  = sm + OS_KVT;
    float* qs   = sm + OS_QS;
    float* ob   = qs;
    float (*vext)[64] = (float(*)[64])(sm + OS_VX);
    float* wds  = sm + OS_WD;

    const int bh = blockIdx.y;
    const int bb = bh / HH;
    const int h  = bh % HH;
    const int s0 = blockIdx.x * 64;

    const float* Qb = g_q + (size_t)bh * SZ * HD;
    const float* Vb = g_v + (size_t)bh * SZ * HD;
    const float* KVb = g_kv + (size_t)bh * HD * HD;

    const int tid = threadIdx.x;
    const int wid = tid >> 5, lane = tid & 31;
    const int l4 = lane >> 2, lk = lane & 3;
    const int wm = wid & 1, wn = wid >> 1;

#pragma unroll
    for (int i = tid * 4; i < 4096; i += 1024) {
        const int d = i >> 6, e = i & 63;
        float4 kvv = *(const float4*)(KVb + i);
        kvT[(e + 0) * 68 + d] = tf32r(kvv.x);
        kvT[(e + 1) * 68 + d] = tf32r(kvv.y);
        kvT[(e + 2) * 68 + d] = tf32r(kvv.z);
        kvT[(e + 3) * 68 + d] = tf32r(kvv.w);
    }

#pragma unroll
    for (int i = tid * 4; i < 4096; i += 1024) {
        const int r = i >> 6, c = i & 63;
        float4 qv = *(const float4*)(Qb + (size_t)(s0 + r) * 64 + c);
        qv.x = tf32r(qv.x); qv.y = tf32r(qv.y);
        qv.z = tf32r(qv.z); qv.w = tf32r(qv.w);
        *(float4*)(qs + r * 68 + c) = qv;
    }

    for (int i = tid * 4; i < 72 * 64; i += 1024) {
        const int r = i >> 6, c = i & 63;
        const int gs = s0 - 4 + r;
        float4 val = make_float4(0.f, 0.f, 0.f, 0.f);
        if (gs >= 0 && gs < SZ)
            val = *(const float4*)(Vb + (size_t)gs * 64 + c);
        *(float4*)&vext[r][c] = val;
    }
    if (tid < KSZ) wds[tid] = wd[h * KSZ + tid];
    __syncthreads();

    float acc[2][2][4];
#pragma unroll
    for (int mi = 0; mi < 2; mi++)
#pragma unroll
        for (int ni = 0; ni < 2; ni++)
#pragma unroll
            for (int r = 0; r < 4; r++) acc[mi][ni][r] = 0.f;

#pragma unroll
    for (int kk = 0; kk < 8; kk++) {
        const int d = kk * 8 + lk;
        uint32_t af[2][4], bf[2][2];
#pragma unroll
        for (int mi = 0; mi < 2; mi++) {
            const int m0 = wm * 32 + mi * 16 + l4;
            af[mi][0] = __float_as_uint(qs[m0 * 68 + d]);
            af[mi][1] = __float_as_uint(qs[(m0 + 8) * 68 + d]);
            af[mi][2] = __float_as_uint(qs[m0 * 68 + d + 4]);
            af[mi][3] = __float_as_uint(qs[(m0 + 8) * 68 + d + 4]);
        }
#pragma unroll
        for (int ni = 0; ni < 2; ni++) {
            const int n0 = wn * 16 + ni * 8 + l4;
            bf[ni][0] = __float_as_uint(kvT[n0 * 68 + d]);
            bf[ni][1] = __float_as_uint(kvT[n0 * 68 + d + 4]);
        }
#pragma unroll
        for (int mi = 0; mi < 2; mi++)
#pragma unroll
            for (int ni = 0; ni < 2; ni++)
                mma_tf32(acc[mi][ni], af[mi][0], af[mi][1], af[mi][2],
                         af[mi][3], bf[ni][0], bf[ni][1]);
    }
    __syncthreads();

#pragma unroll
    for (int mi = 0; mi < 2; mi++)
#pragma unroll
        for (int ni = 0; ni < 2; ni++) {
            const int r = wm * 32 + mi * 16 + l4;
            const int cc = wn * 16 + ni * 8 + lk * 2;
            ob[r * 68 + cc]           = acc[mi][ni][0];
            ob[r * 68 + cc + 1]       = acc[mi][ni][1];
            ob[(r + 8) * 68 + cc]     = acc[mi][ni][2];
            ob[(r + 8) * 68 + cc + 1] = acc[mi][ni][3];
        }
    __syncthreads();

    const float INV_PI = 0.3183098861837907f;
#pragma unroll
    for (int k = 0; k < 8; k++) {
        const int rr = wid * 8 + k;
        const float v0 = 0.5f * vext[rr + 4][lane]      + INV_PI * ob[rr * 68 + lane];
        const float v1 = 0.5f * vext[rr + 4][lane + 32] + INV_PI * ob[rr * 68 + lane + 32];
        float ss = v0 * v0 + v1 * v1;
#pragma unroll
        for (int o = 16; o; o >>= 1) ss += __shfl_xor_sync(0xffffffffu, ss, o);
        const float rn = rsqrtf(ss);
        float c0 = 0.f, c1 = 0.f;
#pragma unroll
        for (int j = 0; j < KSZ; j++) {
            const float w = wds[j];
            c0 += vext[rr + j][lane] * w;
            c1 += vext[rr + j][lane + 32] * w;
        }
        const int sg = s0 + rr;
        __half* dst = g_y + ((size_t)bb * SZ + sg) * DZ + h * HD;
        dst[lane]      = __float2half_rn(v0 * rn + c0);
        dst[lane + 32] = __float2half_rn(v1 * rn + c1);
    }
}

// ---------------------------------------------------------------------------
extern "C" void kernel_launch(void* const* d_in, const int* in_sizes, int n_in,
                              void* d_out, int out_size)
{
    const float* x      = (const float*)d_in[0];
    const float* w_qkv  = (const float*)d_in[1];
    const float* b_qkv  = (const float*)d_in[2];
    const float* w_proj = (const float*)d_in[3];
    const float* b_proj = (const float*)d_in[4];
    const float* w_dcv  = (const float*)d_in[5];
    float* out = (float*)d_out;

    cudaFuncSetAttribute(gemm_mma<1, KDIM/BKT>, cudaFuncAttributeMaxDynamicSharedMemorySize, GEMM_SMEM);
    cudaFuncSetAttribute(gemm_mma<0, KDIM/BKT>, cudaFuncAttributeMaxDynamicSharedMemorySize, GEMM_SMEM);
    cudaFuncSetAttribute(out_kernel, cudaFuncAttributeMaxDynamicSharedMemorySize, OUT_SMEM_BYTES);

    // fp16-convert all GEMM inputs in one launch (RN, unbiased)
    const int n4_total = N4_X + N4_WQ + N4_WP;
    cvt_all<<<(n4_total + 255) / 256, 256>>>((const float4*)x,
                                             (const float4*)w_qkv,
                                             (const float4*)w_proj);

    // QKV projection (fp16 mma, BKT=64) + fused bias + q/k normalize + scatter
    gemm_mma<1, KDIM/BKT><<<dim3(3 * DZ / BNT, MTOT / BMT), 256, GEMM_SMEM>>>(b_qkv, nullptr);
    // kv = k^T v: 4 deterministic S-partials + reduce (tf32)
    kv_mma<<<dim3(4, BZ * HH), 256>>>();
    kv_reduce<<<(BZ * HH * HD * HD) / 1024, 256>>>();
    // angular attention core (tf32) + norm + dconv + relayout -> fp16 g_y
    out_kernel<<<dim3(SZ / 64, BZ * HH), 256, OUT_SMEM_BYTES>>>(w_dcv);
    // output projection (fp16 mma, BKT=64)
    gemm_mma<0, KDIM/BKT><<<dim3(DZ / BNT, MTOT / BMT), 256, GEMM_SMEM>>>(b_proj, out);
}

// round 16
// speedup vs baseline: 1.1378x; 1.0220x over previous
#include <cuda_runtime.h>
#include <cuda_fp16.h>
#include <cstdint>

// ---------------------------------------------------------------------------
// Problem constants
// ---------------------------------------------------------------------------
#define BZ 16
#define SZ 4096
#define DZ 768
#define HH 12
#define HD 64
#define KSZ 9
#define MTOT (BZ*SZ)          // 65536
#define KDIM 768

// Scratch (static device globals; no allocation allowed)
__device__ __align__(256) __half g_q[(size_t)BZ*HH*SZ*HD];   // fp16 (normalized)
__device__ __align__(256) __half g_k[(size_t)BZ*HH*SZ*HD];   // fp16 (normalized)
__device__ __align__(256) __half g_v[(size_t)BZ*HH*SZ*HD];   // fp16
__device__ __align__(256) float g_kv[(size_t)BZ*HH*HD*HD];
__device__ __align__(256) float g_kvp[(size_t)4*BZ*HH*HD*HD];
__device__ __align__(256) __half g_y[(size_t)BZ*SZ*DZ];      // fp16 attn output
__device__ __align__(256) __half g_xc[(size_t)MTOT*KDIM];    // fp16 x
__device__ __align__(256) __half g_wq[(size_t)3*DZ*KDIM];    // fp16 w_qkv
__device__ __align__(256) __half g_wp[(size_t)DZ*KDIM];      // fp16 w_proj

__device__ __forceinline__ float tf32r(float x) {
    uint32_t u;
    asm("cvt.rna.tf32.f32 %0, %1;" : "=r"(u) : "f"(x));
    return __uint_as_float(u);
}

// ---------------------------------------------------------------------------
// Single fused fp16 conversion kernel over x | w_qkv | w_proj (RN, unbiased)
// ---------------------------------------------------------------------------
#define N4_X  (MTOT*KDIM/4)
#define N4_WQ (3*DZ*KDIM/4)
#define N4_WP (DZ*KDIM/4)
__global__ void cvt_all(const float4* __restrict__ x,
                        const float4* __restrict__ wq,
                        const float4* __restrict__ wp)
{
    int i = blockIdx.x * blockDim.x + threadIdx.x;
    const float4* src; __half* dst;
    if (i < N4_X) { src = x + i; dst = g_xc + (size_t)i * 4; }
    else if (i < N4_X + N4_WQ) { i -= N4_X; src = wq + i; dst = g_wq + (size_t)i * 4; }
    else if (i < N4_X + N4_WQ + N4_WP) { i -= N4_X + N4_WQ; src = wp + i; dst = g_wp + (size_t)i * 4; }
    else return;
    float4 v = *src;
    __half2 h01 = __floats2half2_rn(v.x, v.y);
    __half2 h23 = __floats2half2_rn(v.z, v.w);
    uint2 o;
    o.x = *(uint32_t*)&h01;
    o.y = *(uint32_t*)&h23;
    *(uint2*)dst = o;
}

// fp16 mma m16n8k16, fp32 accumulate
__device__ __forceinline__ void mma_f16(float* c, uint32_t a0, uint32_t a1,
                                        uint32_t a2, uint32_t a3,
                                        uint32_t b0, uint32_t b1)
{
    asm volatile("mma.sync.aligned.m16n8k16.row.col.f32.f16.f16.f32 "
                 "{%0,%1,%2,%3}, {%4,%5,%6,%7}, {%8,%9}, {%0,%1,%2,%3};"
                 : "+f"(c[0]), "+f"(c[1]), "+f"(c[2]), "+f"(c[3])
                 : "r"(a0), "r"(a1), "r"(a2), "r"(a3), "r"(b0), "r"(b1));
}

// tf32 mma m16n8k8 (kv + out kernels)
__device__ __forceinline__ void mma_tf32(float* c, uint32_t a0, uint32_t a1,
                                         uint32_t a2, uint32_t a3,
                                         uint32_t b0, uint32_t b1)
{
    asm volatile("mma.sync.aligned.m16n8k8.row.col.f32.tf32.tf32.f32 "
                 "{%0,%1,%2,%3}, {%4,%5,%6,%7}, {%8,%9}, {%0,%1,%2,%3};"
                 : "+f"(c[0]), "+f"(c[1]), "+f"(c[2]), "+f"(c[3])
                 : "r"(a0), "r"(a1), "r"(a2), "r"(a3), "r"(b0), "r"(b1));
}

__device__ __forceinline__ void ldsm_x4(uint32_t* r, uint32_t addr)
{
    asm volatile("ldmatrix.sync.aligned.m8n8.x4.shared.b16 {%0,%1,%2,%3}, [%4];"
                 : "=r"(r[0]), "=r"(r[1]), "=r"(r[2]), "=r"(r[3]) : "r"(addr));
}

// ---------------------------------------------------------------------------
// FP16 mma.sync GEMM: C[m,n] = sum_k A[m,k]*W[n,k] + bias[n]
// 128x128x64 CTA tile (12 chunks), 3-stage cp.async ring, 2 CTAs/SM,
// 8 warps @ 64x32. SKAh=72 (conflict-free; 16B-aligned cp.async dsts).
// ---------------------------------------------------------------------------
#define BMT 128
#define BNT 128
#define BKT 64
#define NSTG 3
#define SKAh 72
#define STG_HALVES (2*BMT*SKAh)          // 18432 halves / stage
#define STG_BYTES  (STG_HALVES*2)        // 36864
#define GEMM_SMEM  (NSTG*STG_BYTES)      // 110592
#define EPI_STRIDE 132

__device__ __forceinline__ void stage_load(uint32_t sb, const __half* Abase,
                                           const __half* Bbase, int ko, int tid)
{
#pragma unroll
    for (int j = 0; j < 4; j++) {
        const int idx = tid + j * 256;        // 0..1023
        const int row = idx >> 3;             // 0..127
        const int c16 = (idx & 7) * 8;        // half offset within row (0..56)
        const __half* ga = Abase + (size_t)row * KDIM + ko + c16;
        const __half* gb = Bbase + (size_t)row * KDIM + ko + c16;
        asm volatile("cp.async.cg.shared.global [%0], [%1], 16;"
                     :: "r"(sb + (row * SKAh + c16) * 2), "l"(ga));
        asm volatile("cp.async.cg.shared.global [%0], [%1], 16;"
                     :: "r"(sb + (BMT * SKAh + row * SKAh + c16) * 2), "l"(gb));
    }
    asm volatile("cp.async.commit_group;");
}

template<int MODE, int NCHUNK>
__global__ __launch_bounds__(256, 2)
void gemm_mma(const float* __restrict__ bias, float* __restrict__ Cout)
{
    extern __shared__ __align__(16) float smf[];
    __shared__ float sbias[BNT];

    const int tid  = threadIdx.x;
    const int wid  = tid >> 5;
    const int lane = tid & 31;
    const int l4   = lane >> 2;
    const int lk   = lane & 3;
    const int warpM = wid & 1;
    const int warpN = wid >> 1;

    const int bn = blockIdx.x * BNT;
    const int bm = blockIdx.y * BMT;

    const __half* A = (MODE == 1) ? g_xc : g_y;
    const __half* W = (MODE == 1) ? g_wq : g_wp;
    const __half* Abase = A + (size_t)bm * KDIM;
    const __half* Bbase = W + (size_t)bn * KDIM;

    if (tid < BNT) sbias[tid] = bias[bn + tid];

    uint32_t sm_u32;
    asm("{ .reg .u64 t; cvta.to.shared.u64 t, %1; cvt.u32.u64 %0, t; }"
        : "=r"(sm_u32) : "l"(smf));

    // ldmatrix per-thread addresses (b16 fragments, fp16 m16n8k16)
    const int aRow = warpM * 64 + (lane & 15);
    const int aColH = (lane >> 4) * 8;
    const uint32_t aOff = (aRow * SKAh + aColH) * 2;
    const int bRow = warpN * 32 + (lane & 7) + ((lane >> 4) & 1) * 8;
    const int bColH = ((lane >> 3) & 1) * 8;
    const uint32_t bOff = (BMT * SKAh + bRow * SKAh + bColH) * 2;

    // prologue: prefetch 2 stages
    stage_load(sm_u32, Abase, Bbase, 0, tid);
    stage_load(sm_u32 + STG_BYTES, Abase, Bbase, BKT, tid);

    float acc[4][4][4];
#pragma unroll
    for (int mi = 0; mi < 4; mi++)
#pragma unroll
        for (int ni = 0; ni < 4; ni++)
#pragma unroll
            for (int r = 0; r < 4; r++) acc[mi][ni][r] = 0.f;

    int st_c = 0;
    for (int c = 0; c < NCHUNK; c++) {
        asm volatile("cp.async.wait_group %0;" :: "n"(1));
        __syncthreads();

        const uint32_t aAddr = sm_u32 + st_c * STG_BYTES + aOff;
        const uint32_t bAddr = sm_u32 + st_c * STG_BYTES + bOff;

#pragma unroll
        for (int kk = 0; kk < 4; kk++) {
            uint32_t af[4][4], bf[2][4];
#pragma unroll
            for (int mi = 0; mi < 4; mi++)
                ldsm_x4(af[mi], aAddr + (mi * 16 * SKAh + kk * 16) * 2);
#pragma unroll
            for (int pp = 0; pp < 2; pp++)
                ldsm_x4(bf[pp], bAddr + (pp * 16 * SKAh + kk * 16) * 2);
#pragma unroll
            for (int mi = 0; mi < 4; mi++)
#pragma unroll
                for (int ni = 0; ni < 4; ni++)
                    mma_f16(acc[mi][ni], af[mi][0], af[mi][1], af[mi][2],
                            af[mi][3], bf[ni >> 1][(ni & 1) * 2],
                            bf[ni >> 1][(ni & 1) * 2 + 1]);
        }

        // prefetch chunk c+2 (after the MMA block)
        const int stp = st_c ? st_c - 1 : 2;
        if (c + 2 < NCHUNK)
            stage_load(sm_u32 + stp * STG_BYTES, Abase, Bbase, (c + 2) * BKT, tid);
        else
            asm volatile("cp.async.commit_group;");
        st_c = (st_c == 2) ? 0 : st_c + 1;
    }

    // ---- epilogue (fp32 math) ----
    asm volatile("cp.async.wait_group %0;" :: "n"(0));
    __syncthreads();
    float* st = smf;
#pragma unroll
    for (int mi = 0; mi < 4; mi++)
#pragma unroll
        for (int ni = 0; ni < 4; ni++) {
            const int r = warpM * 64 + mi * 16 + l4;
            const int cc = warpN * 32 + ni * 8 + lk * 2;
            st[r * EPI_STRIDE + cc]           = acc[mi][ni][0];
            st[r * EPI_STRIDE + cc + 1]       = acc[mi][ni][1];
            st[(r + 8) * EPI_STRIDE + cc]     = acc[mi][ni][2];
            st[(r + 8) * EPI_STRIDE + cc + 1] = acc[mi][ni][3];
        }
    __syncthreads();

    if (MODE == 0) {
#pragma unroll 1
        for (int i = 0; i < 16; i++) {
            const int r = wid * 16 + i;
            float4 u = *(const float4*)(st + (size_t)r * EPI_STRIDE + lane * 4);
            u.x += sbias[lane * 4];     u.y += sbias[lane * 4 + 1];
            u.z += sbias[lane * 4 + 2]; u.w += sbias[lane * 4 + 3];
            *(float4*)(Cout + (size_t)(bm + r) * DZ + bn + lane * 4) = u;
        }
    } else {
        const int part = bn / DZ;
        const int col0 = bn - part * DZ;
        const int h0 = col0 >> 6;
        __half* dbuf = (part == 0) ? g_q : (part == 1) ? g_k : g_v;
#pragma unroll 1
        for (int i = 0; i < 16; i++) {
            const int r = wid * 16 + i;
            const int m = bm + r;
            const int b = m >> 12;
            const int s = m & (SZ - 1);
            float2 u0 = *(const float2*)(st + (size_t)r * EPI_STRIDE + lane * 2);
            float2 u1 = *(const float2*)(st + (size_t)r * EPI_STRIDE + 64 + lane * 2);
            u0.x += sbias[lane * 2];      u0.y += sbias[lane * 2 + 1];
            u1.x += sbias[64 + lane * 2]; u1.y += sbias[64 + lane * 2 + 1];
            if (part < 2) {
                float ss0 = u0.x * u0.x + u0.y * u0.y;
                float ss1 = u1.x * u1.x + u1.y * u1.y;
#pragma unroll
                for (int o = 16; o; o >>= 1) {
                    ss0 += __shfl_xor_sync(0xffffffffu, ss0, o);
                    ss1 += __shfl_xor_sync(0xffffffffu, ss1, o);
                }
                const float r0 = rsqrtf(ss0), r1 = rsqrtf(ss1);
                u0.x *= r0; u0.y *= r0;
                u1.x *= r1; u1.y *= r1;
            }
            const size_t base0 = ((((size_t)b * HH + h0) * SZ + s) << 6) + lane * 2;
            const size_t base1 = ((((size_t)b * HH + h0 + 1) * SZ + s) << 6) + lane * 2;
            *(__half2*)(dbuf + base0) = __floats2half2_rn(u0.x, u0.y);
            *(__half2*)(dbuf + base1) = __floats2half2_rn(u1.x, u1.y);
        }
    }
}

// ---------------------------------------------------------------------------
// kv partials: kvp[part][bh] = sum_{s in part} k^T v over 1024 seq positions.
// grid (4, 192); deterministic. k,v read fp16 (exactly representable in tf32,
// so no tf32r needed). Swizzled [d][s] fp32 smem layout (proven fragment code).
// ---------------------------------------------------------------------------
__global__ __launch_bounds__(256) void kv_mma()
{
    __shared__ float ks[64 * 32];
    __shared__ float vs[64 * 32];

    const int part = blockIdx.x;
    const int bh = blockIdx.y;
    const __half* Kb = g_k + (size_t)bh * SZ * HD;
    const __half* Vb = g_v + (size_t)bh * SZ * HD;

    const int tid = threadIdx.x;
    const int wid = tid >> 5, lane = tid & 31;
    const int l4 = lane >> 2, lk = lane & 3;
    const int wm = wid & 1, wn = wid >> 1;

    const int dL = tid & 63;
    const int sg = tid >> 6;
    const int swzL = ((dL & 7) << 2) + (dL >> 3);
    const int sbase = dL * 32;

    const int d0 = wm * 32 + l4;
    const int e0 = wn * 16 + l4;

    float acc[2][2][4];
#pragma unroll
    for (int mi = 0; mi < 2; mi++)
#pragma unroll
        for (int ni = 0; ni < 2; ni++)
#pragma unroll
            for (int r = 0; r < 4; r++) acc[mi][ni][r] = 0.f;

    const int s_lo = part * 1024;
    for (int s0 = s_lo; s0 < s_lo + 1024; s0 += 32) {
        float kr[8], vr[8];
#pragma unroll
        for (int i = 0; i < 8; i++) {
            const int s = s0 + sg + i * 4;
            kr[i] = __half2float(Kb[(size_t)s * 64 + dL]);
            vr[i] = __half2float(Vb[(size_t)s * 64 + dL]);
        }
        __syncthreads();
#pragma unroll
        for (int i = 0; i < 8; i++) {
            const int col = (sg + i * 4 + swzL) & 31;
            ks[sbase + col] = kr[i];
            vs[sbase + col] = vr[i];
        }
        __syncthreads();

#pragma unroll
        for (int kk = 0; kk < 4; kk++) {
            const int c0 = kk * 8 + lk;
            uint32_t af[2][4], bf[2][2];
#pragma unroll
            for (int mi = 0; mi < 2; mi++) {
                const int da = d0 + mi * 16;
                const int db = da + 8;
                const int swa = ((da & 7) << 2) + (da >> 3);
                const int swb = swa + 1;
                af[mi][0] = __float_as_uint(ks[da * 32 + ((c0 + swa) & 31)]);
                af[mi][1] = __float_as_uint(ks[db * 32 + ((c0 + swb) & 31)]);
                af[mi][2] = __float_as_uint(ks[da * 32 + ((c0 + 4 + swa) & 31)]);
                af[mi][3] = __float_as_uint(ks[db * 32 + ((c0 + 4 + swb) & 31)]);
            }
#pragma unroll
            for (int ni = 0; ni < 2; ni++) {
                const int ea = e0 + ni * 8;
                const int swe = ((ea & 7) << 2) + (ea >> 3);
                bf[ni][0] = __float_as_uint(vs[ea * 32 + ((c0 + swe) & 31)]);
                bf[ni][1] = __float_as_uint(vs[ea * 32 + ((c0 + 4 + swe) & 31)]);
            }
#pragma unroll
            for (int mi = 0; mi < 2; mi++)
#pragma unroll
                for (int ni = 0; ni < 2; ni++)
                    mma_tf32(acc[mi][ni], af[mi][0], af[mi][1], af[mi][2],
                             af[mi][3], bf[ni][0], bf[ni][1]);
        }
    }

    float* out = g_kvp + ((size_t)part * BZ * HH + bh) * HD * HD;
#pragma unroll
    for (int mi = 0; mi < 2; mi++)
#pragma unroll
        for (int ni = 0; ni < 2; ni++) {
            const int d = wm * 32 + mi * 16 + l4;
            const int e = wn * 16 + ni * 8 + lk * 2;
            *(float2*)&out[d * 64 + e]       = make_float2(acc[mi][ni][0], acc[mi][ni][1]);
            *(float2*)&out[(d + 8) * 64 + e] = make_float2(acc[mi][ni][2], acc[mi][ni][3]);
        }
}

// Sum the 4 kv partials into g_kv.
__global__ void kv_reduce()
{
    const size_t i = ((size_t)blockIdx.x * blockDim.x + threadIdx.x) * 4;
    const size_t stride = (size_t)BZ * HH * HD * HD;
    float4 a = *(const float4*)&g_kvp[i];
    float4 b = *(const float4*)&g_kvp[i + stride];
    float4 c = *(const float4*)&g_kvp[i + 2 * stride];
    float4 d = *(const float4*)&g_kvp[i + 3 * stride];
    a.x += b.x + c.x + d.x;  a.y += b.y + c.y + d.y;
    a.z += b.z + c.z + d.z;  a.w += b.w + c.w + d.w;
    *(float4*)&g_kv[i] = a;
}

// ---------------------------------------------------------------------------
// out = normalize(0.5*v + (1/pi) q@kv) + dconv(v); q@kv via tf32 mma.sync.
// q,v read fp16 (tf32-exact). smem: kvT[64][68] | qs[64][68] (aliased ob) |
// vext[72][64]; g_y stored fp16.
// ---------------------------------------------------------------------------
#define OS_KVT 0
#define OS_QS  (64*68)
#define OS_VX  (2*64*68)
#define OS_WD  (2*64*68 + 72*64)
#define OUT_SMEM_FLOATS (2*64*68 + 72*64 + 16)
#define OUT_SMEM_BYTES  (OUT_SMEM_FLOATS * 4)

__global__ __launch_bounds__(256) void out_kernel(const float* __restrict__ wd)
{
    extern __shared__ float sm[];
    float* kvT  = sm + OS_KVT;
    float* qs   = sm + OS_QS;
    float* ob   = qs;
    float (*vext)[64] = (float(*)[64])(sm + OS_VX);
    float* wds  = sm + OS_WD;

    const int bh = blockIdx.y;
    const int bb = bh / HH;
    const int h  = bh % HH;
    const int s0 = blockIdx.x * 64;

    const __half* Qb = g_q + (size_t)bh * SZ * HD;
    const __half* Vb = g_v + (size_t)bh * SZ * HD;
    const float* KVb = g_kv + (size_t)bh * HD * HD;

    const int tid = threadIdx.x;
    const int wid = tid >> 5, lane = tid & 31;
    const int l4 = lane >> 2, lk = lane & 3;
    const int wm = wid & 1, wn = wid >> 1;

    // kv (fp32) -> kvT transposed, tf32-rounded
#pragma unroll
    for (int i = tid * 4; i < 4096; i += 1024) {
        const int d = i >> 6, e = i & 63;
        float4 kvv = *(const float4*)(KVb + i);
        kvT[(e + 0) * 68 + d] = tf32r(kvv.x);
        kvT[(e + 1) * 68 + d] = tf32r(kvv.y);
        kvT[(e + 2) * 68 + d] = tf32r(kvv.z);
        kvT[(e + 3) * 68 + d] = tf32r(kvv.w);
    }

    // q (fp16, tf32-exact) -> qs
#pragma unroll
    for (int i = tid * 4; i < 4096; i += 1024) {
        const int r = i >> 6, c = i & 63;
        uint2 u = *(const uint2*)(Qb + (size_t)(s0 + r) * 64 + c);
        float2 f0 = __half22float2(*(__half2*)&u.x);
        float2 f1 = __half22float2(*(__half2*)&u.y);
        *(float4*)(qs + r * 68 + c) = make_float4(f0.x, f0.y, f1.x, f1.y);
    }

    // v (fp16) with +-4 halo
    for (int i = tid * 4; i < 72 * 64; i += 1024) {
        const int r = i >> 6, c = i & 63;
        const int gs = s0 - 4 + r;
        float4 val = make_float4(0.f, 0.f, 0.f, 0.f);
        if (gs >= 0 && gs < SZ) {
            uint2 u = *(const uint2*)(Vb + (size_t)gs * 64 + c);
            float2 f0 = __half22float2(*(__half2*)&u.x);
            float2 f1 = __half22float2(*(__half2*)&u.y);
            val = make_float4(f0.x, f0.y, f1.x, f1.y);
        }
        *(float4*)&vext[r][c] = val;
    }
    if (tid < KSZ) wds[tid] = wd[h * KSZ + tid];
    __syncthreads();

    float acc[2][2][4];
#pragma unroll
    for (int mi = 0; mi < 2; mi++)
#pragma unroll
        for (int ni = 0; ni < 2; ni++)
#pragma unroll
            for (int r = 0; r < 4; r++) acc[mi][ni][r] = 0.f;

#pragma unroll
    for (int kk = 0; kk < 8; kk++) {
        const int d = kk * 8 + lk;
        uint32_t af[2][4], bf[2][2];
#pragma unroll
        for (int mi = 0; mi < 2; mi++) {
            const int m0 = wm * 32 + mi * 16 + l4;
            af[mi][0] = __float_as_uint(qs[m0 * 68 + d]);
            af[mi][1] = __float_as_uint(qs[(m0 + 8) * 68 + d]);
            af[mi][2] = __float_as_uint(qs[m0 * 68 + d + 4]);
            af[mi][3] = __float_as_uint(qs[(m0 + 8) * 68 + d + 4]);
        }
#pragma unroll
        for (int ni = 0; ni < 2; ni++) {
            const int n0 = wn * 16 + ni * 8 + l4;
            bf[ni][0] = __float_as_uint(kvT[n0 * 68 + d]);
            bf[ni][1] = __float_as_uint(kvT[n0 * 68 + d + 4]);
        }
#pragma unroll
        for (int mi = 0; mi < 2; mi++)
#pragma unroll
            for (int ni = 0; ni < 2; ni++)
                mma_tf32(acc[mi][ni], af[mi][0], af[mi][1], af[mi][2],
                         af[mi][3], bf[ni][0], bf[ni][1]);
    }
    __syncthreads();

#pragma unroll
    for (int mi = 0; mi < 2; mi++)
#pragma unroll
        for (int ni = 0; ni < 2; ni++) {
            const int r = wm * 32 + mi * 16 + l4;
            const int cc = wn * 16 + ni * 8 + lk * 2;
            ob[r * 68 + cc]           = acc[mi][ni][0];
            ob[r * 68 + cc + 1]       = acc[mi][ni][1];
            ob[(r + 8) * 68 + cc]     = acc[mi][ni][2];
            ob[(r + 8) * 68 + cc + 1] = acc[mi][ni][3];
        }
    __syncthreads();

    const float INV_PI = 0.3183098861837907f;
#pragma unroll
    for (int k = 0; k < 8; k++) {
        const int rr = wid * 8 + k;
        const float v0 = 0.5f * vext[rr + 4][lane]      + INV_PI * ob[rr * 68 + lane];
        const float v1 = 0.5f * vext[rr + 4][lane + 32] + INV_PI * ob[rr * 68 + lane + 32];
        float ss = v0 * v0 + v1 * v1;
#pragma unroll
        for (int o = 16; o; o >>= 1) ss += __shfl_xor_sync(0xffffffffu, ss, o);
        const float rn = rsqrtf(ss);
        float c0 = 0.f, c1 = 0.f;
#pragma unroll
        for (int j = 0; j < KSZ; j++) {
            const float w = wds[j];
            c0 += vext[rr + j][lane] * w;
            c1 += vext[rr + j][lane + 32] * w;
        }
        const int sg = s0 + rr;
        __half* dst = g_y + ((size_t)bb * SZ + sg) * DZ + h * HD;
        dst[lane]      = __float2half_rn(v0 * rn + c0);
        dst[lane + 32] = __float2half_rn(v1 * rn + c1);
    }
}

// ---------------------------------------------------------------------------
extern "C" void kernel_launch(void* const* d_in, const int* in_sizes, int n_in,
                              void* d_out, int out_size)
{
    const float* x      = (const float*)d_in[0];
    const float* w_qkv  = (const float*)d_in[1];
    const float* b_qkv  = (const float*)d_in[2];
    const float* w_proj = (const float*)d_in[3];
    const float* b_proj = (const float*)d_in[4];
    const float* w_dcv  = (const float*)d_in[5];
    float* out = (float*)d_out;

    cudaFuncSetAttribute(gemm_mma<1, KDIM/BKT>, cudaFuncAttributeMaxDynamicSharedMemorySize, GEMM_SMEM);
    cudaFuncSetAttribute(gemm_mma<0, KDIM/BKT>, cudaFuncAttributeMaxDynamicSharedMemorySize, GEMM_SMEM);
    cudaFuncSetAttribute(out_kernel, cudaFuncAttributeMaxDynamicSharedMemorySize, OUT_SMEM_BYTES);

    // fp16-convert all GEMM inputs in one launch (RN, unbiased)
    const int n4_total = N4_X + N4_WQ + N4_WP;
    cvt_all<<<(n4_total + 255) / 256, 256>>>((const float4*)x,
                                             (const float4*)w_qkv,
                                             (const float4*)w_proj);

    // QKV projection (fp16 mma) + fused bias + q/k normalize + fp16 scatter
    gemm_mma<1, KDIM/BKT><<<dim3(3 * DZ / BNT, MTOT / BMT), 256, GEMM_SMEM>>>(b_qkv, nullptr);
    // kv = k^T v: 4 deterministic S-partials + reduce (tf32 on fp16 inputs)
    kv_mma<<<dim3(4, BZ * HH), 256>>>();
    kv_reduce<<<(BZ * HH * HD * HD) / 1024, 256>>>();
    // angular attention core (tf32) + norm + dconv + relayout -> fp16 g_y
    out_kernel<<<dim3(SZ / 64, BZ * HH), 256, OUT_SMEM_BYTES>>>(w_dcv);
    // output projection (fp16 mma)
    gemm_mma<0, KDIM/BKT><<<dim3(DZ / BNT, MTOT / BMT), 256, GEMM_SMEM>>>(b_proj, out);
}

// round 17
// speedup vs baseline: 1.2081x; 1.0617x over previous
#include <cuda_runtime.h>
#include <cuda_fp16.h>
#include <cstdint>

// ---------------------------------------------------------------------------
// Problem constants
// ---------------------------------------------------------------------------
#define BZ 16
#define SZ 4096
#define DZ 768
#define HH 12
#define HD 64
#define KSZ 9
#define MTOT (BZ*SZ)          // 65536
#define KDIM 768

// Scratch (static device globals; no allocation allowed)
__device__ __align__(256) __half g_q[(size_t)BZ*HH*SZ*HD];   // fp16 (normalized)
__device__ __align__(256) __half g_k[(size_t)BZ*HH*SZ*HD];   // fp16 (normalized)
__device__ __align__(256) __half g_v[(size_t)BZ*HH*SZ*HD];   // fp16
__device__ __align__(256) __half g_kvh[(size_t)BZ*HH*HD*HD]; // fp16 kv
__device__ __align__(256) float g_kvp[(size_t)4*BZ*HH*HD*HD];
__device__ __align__(256) __half g_y[(size_t)BZ*SZ*DZ];      // fp16 attn output
__device__ __align__(256) __half g_xc[(size_t)MTOT*KDIM];    // fp16 x
__device__ __align__(256) __half g_wq[(size_t)3*DZ*KDIM];    // fp16 w_qkv
__device__ __align__(256) __half g_wp[(size_t)DZ*KDIM];      // fp16 w_proj

__device__ __forceinline__ float tf32r(float x) {
    uint32_t u;
    asm("cvt.rna.tf32.f32 %0, %1;" : "=r"(u) : "f"(x));
    return __uint_as_float(u);
}

// ---------------------------------------------------------------------------
// Single fused fp16 conversion kernel over x | w_qkv | w_proj (RN, unbiased)
// ---------------------------------------------------------------------------
#define N4_X  (MTOT*KDIM/4)
#define N4_WQ (3*DZ*KDIM/4)
#define N4_WP (DZ*KDIM/4)
__global__ void cvt_all(const float4* __restrict__ x,
                        const float4* __restrict__ wq,
                        const float4* __restrict__ wp)
{
    int i = blockIdx.x * blockDim.x + threadIdx.x;
    const float4* src; __half* dst;
    if (i < N4_X) { src = x + i; dst = g_xc + (size_t)i * 4; }
    else if (i < N4_X + N4_WQ) { i -= N4_X; src = wq + i; dst = g_wq + (size_t)i * 4; }
    else if (i < N4_X + N4_WQ + N4_WP) { i -= N4_X + N4_WQ; src = wp + i; dst = g_wp + (size_t)i * 4; }
    else return;
    float4 v = *src;
    __half2 h01 = __floats2half2_rn(v.x, v.y);
    __half2 h23 = __floats2half2_rn(v.z, v.w);
    uint2 o;
    o.x = *(uint32_t*)&h01;
    o.y = *(uint32_t*)&h23;
    *(uint2*)dst = o;
}

// fp16 mma m16n8k16, fp32 accumulate
__device__ __forceinline__ void mma_f16(float* c, uint32_t a0, uint32_t a1,
                                        uint32_t a2, uint32_t a3,
                                        uint32_t b0, uint32_t b1)
{
    asm volatile("mma.sync.aligned.m16n8k16.row.col.f32.f16.f16.f32 "
                 "{%0,%1,%2,%3}, {%4,%5,%6,%7}, {%8,%9}, {%0,%1,%2,%3};"
                 : "+f"(c[0]), "+f"(c[1]), "+f"(c[2]), "+f"(c[3])
                 : "r"(a0), "r"(a1), "r"(a2), "r"(a3), "r"(b0), "r"(b1));
}

// tf32 mma m16n8k8 (kv + out kernels)
__device__ __forceinline__ void mma_tf32(float* c, uint32_t a0, uint32_t a1,
                                         uint32_t a2, uint32_t a3,
                                         uint32_t b0, uint32_t b1)
{
    asm volatile("mma.sync.aligned.m16n8k8.row.col.f32.tf32.tf32.f32 "
                 "{%0,%1,%2,%3}, {%4,%5,%6,%7}, {%8,%9}, {%0,%1,%2,%3};"
                 : "+f"(c[0]), "+f"(c[1]), "+f"(c[2]), "+f"(c[3])
                 : "r"(a0), "r"(a1), "r"(a2), "r"(a3), "r"(b0), "r"(b1));
}

__device__ __forceinline__ void ldsm_x4(uint32_t* r, uint32_t addr)
{
    asm volatile("ldmatrix.sync.aligned.m8n8.x4.shared.b16 {%0,%1,%2,%3}, [%4];"
                 : "=r"(r[0]), "=r"(r[1]), "=r"(r[2]), "=r"(r[3]) : "r"(addr));
}

// ---------------------------------------------------------------------------
// FP16 mma.sync GEMM: C[m,n] = sum_k A[m,k]*W[n,k] + bias[n]
// 128x128x64 CTA tile (12 chunks), 3-stage cp.async ring, 2 CTAs/SM,
// 8 warps @ 64x32. SKAh=72 (conflict-free; 16B-aligned cp.async dsts).
// ---------------------------------------------------------------------------
#define BMT 128
#define BNT 128
#define BKT 64
#define NSTG 3
#define SKAh 72
#define STG_HALVES (2*BMT*SKAh)          // 18432 halves / stage
#define STG_BYTES  (STG_HALVES*2)        // 36864
#define GEMM_SMEM  (NSTG*STG_BYTES)      // 110592
#define EPI_STRIDE 132

__device__ __forceinline__ void stage_load(uint32_t sb, const __half* Abase,
                                           const __half* Bbase, int ko, int tid)
{
#pragma unroll
    for (int j = 0; j < 4; j++) {
        const int idx = tid + j * 256;        // 0..1023
        const int row = idx >> 3;             // 0..127
        const int c16 = (idx & 7) * 8;        // half offset within row (0..56)
        const __half* ga = Abase + (size_t)row * KDIM + ko + c16;
        const __half* gb = Bbase + (size_t)row * KDIM + ko + c16;
        asm volatile("cp.async.cg.shared.global [%0], [%1], 16;"
                     :: "r"(sb + (row * SKAh + c16) * 2), "l"(ga));
        asm volatile("cp.async.cg.shared.global [%0], [%1], 16;"
                     :: "r"(sb + (BMT * SKAh + row * SKAh + c16) * 2), "l"(gb));
    }
    asm volatile("cp.async.commit_group;");
}

template<int MODE, int NCHUNK>
__global__ __launch_bounds__(256, 2)
void gemm_mma(const float* __restrict__ bias, float* __restrict__ Cout)
{
    extern __shared__ __align__(16) float smf[];
    __shared__ float sbias[BNT];

    const int tid  = threadIdx.x;
    const int wid  = tid >> 5;
    const int lane = tid & 31;
    const int l4   = lane >> 2;
    const int lk   = lane & 3;
    const int warpM = wid & 1;
    const int warpN = wid >> 1;

    const int bn = blockIdx.x * BNT;
    const int bm = blockIdx.y * BMT;

    const __half* A = (MODE == 1) ? g_xc : g_y;
    const __half* W = (MODE == 1) ? g_wq : g_wp;
    const __half* Abase = A + (size_t)bm * KDIM;
    const __half* Bbase = W + (size_t)bn * KDIM;

    if (tid < BNT) sbias[tid] = bias[bn + tid];

    uint32_t sm_u32;
    asm("{ .reg .u64 t; cvta.to.shared.u64 t, %1; cvt.u32.u64 %0, t; }"
        : "=r"(sm_u32) : "l"(smf));

    // ldmatrix per-thread addresses (b16 fragments, fp16 m16n8k16)
    const int aRow = warpM * 64 + (lane & 15);
    const int aColH = (lane >> 4) * 8;
    const uint32_t aOff = (aRow * SKAh + aColH) * 2;
    const int bRow = warpN * 32 + (lane & 7) + ((lane >> 4) & 1) * 8;
    const int bColH = ((lane >> 3) & 1) * 8;
    const uint32_t bOff = (BMT * SKAh + bRow * SKAh + bColH) * 2;

    // prologue: prefetch 2 stages
    stage_load(sm_u32, Abase, Bbase, 0, tid);
    stage_load(sm_u32 + STG_BYTES, Abase, Bbase, BKT, tid);

    float acc[4][4][4];
#pragma unroll
    for (int mi = 0; mi < 4; mi++)
#pragma unroll
        for (int ni = 0; ni < 4; ni++)
#pragma unroll
            for (int r = 0; r < 4; r++) acc[mi][ni][r] = 0.f;

    int st_c = 0;
    for (int c = 0; c < NCHUNK; c++) {
        asm volatile("cp.async.wait_group %0;" :: "n"(1));
        __syncthreads();

        const uint32_t aAddr = sm_u32 + st_c * STG_BYTES + aOff;
        const uint32_t bAddr = sm_u32 + st_c * STG_BYTES + bOff;

#pragma unroll
        for (int kk = 0; kk < 4; kk++) {
            uint32_t af[4][4], bf[2][4];
#pragma unroll
            for (int mi = 0; mi < 4; mi++)
                ldsm_x4(af[mi], aAddr + (mi * 16 * SKAh + kk * 16) * 2);
#pragma unroll
            for (int pp = 0; pp < 2; pp++)
                ldsm_x4(bf[pp], bAddr + (pp * 16 * SKAh + kk * 16) * 2);
#pragma unroll
            for (int mi = 0; mi < 4; mi++)
#pragma unroll
                for (int ni = 0; ni < 4; ni++)
                    mma_f16(acc[mi][ni], af[mi][0], af[mi][1], af[mi][2],
                            af[mi][3], bf[ni >> 1][(ni & 1) * 2],
                            bf[ni >> 1][(ni & 1) * 2 + 1]);
        }

        // prefetch chunk c+2 (after the MMA block)
        const int stp = st_c ? st_c - 1 : 2;
        if (c + 2 < NCHUNK)
            stage_load(sm_u32 + stp * STG_BYTES, Abase, Bbase, (c + 2) * BKT, tid);
        else
            asm volatile("cp.async.commit_group;");
        st_c = (st_c == 2) ? 0 : st_c + 1;
    }

    // ---- epilogue (fp32 math) ----
    asm volatile("cp.async.wait_group %0;" :: "n"(0));
    __syncthreads();
    float* st = smf;
#pragma unroll
    for (int mi = 0; mi < 4; mi++)
#pragma unroll
        for (int ni = 0; ni < 4; ni++) {
            const int r = warpM * 64 + mi * 16 + l4;
            const int cc = warpN * 32 + ni * 8 + lk * 2;
            st[r * EPI_STRIDE + cc]           = acc[mi][ni][0];
            st[r * EPI_STRIDE + cc + 1]       = acc[mi][ni][1];
            st[(r + 8) * EPI_STRIDE + cc]     = acc[mi][ni][2];
            st[(r + 8) * EPI_STRIDE + cc + 1] = acc[mi][ni][3];
        }
    __syncthreads();

    if (MODE == 0) {
#pragma unroll 1
        for (int i = 0; i < 16; i++) {
            const int r = wid * 16 + i;
            float4 u = *(const float4*)(st + (size_t)r * EPI_STRIDE + lane * 4);
            u.x += sbias[lane * 4];     u.y += sbias[lane * 4 + 1];
            u.z += sbias[lane * 4 + 2]; u.w += sbias[lane * 4 + 3];
            *(float4*)(Cout + (size_t)(bm + r) * DZ + bn + lane * 4) = u;
        }
    } else {
        const int part = bn / DZ;
        const int col0 = bn - part * DZ;
        const int h0 = col0 >> 6;
        __half* dbuf = (part == 0) ? g_q : (part == 1) ? g_k : g_v;
#pragma unroll 1
        for (int i = 0; i < 16; i++) {
            const int r = wid * 16 + i;
            const int m = bm + r;
            const int b = m >> 12;
            const int s = m & (SZ - 1);
            float2 u0 = *(const float2*)(st + (size_t)r * EPI_STRIDE + lane * 2);
            float2 u1 = *(const float2*)(st + (size_t)r * EPI_STRIDE + 64 + lane * 2);
            u0.x += sbias[lane * 2];      u0.y += sbias[lane * 2 + 1];
            u1.x += sbias[64 + lane * 2]; u1.y += sbias[64 + lane * 2 + 1];
            if (part < 2) {
                float ss0 = u0.x * u0.x + u0.y * u0.y;
                float ss1 = u1.x * u1.x + u1.y * u1.y;
#pragma unroll
                for (int o = 16; o; o >>= 1) {
                    ss0 += __shfl_xor_sync(0xffffffffu, ss0, o);
                    ss1 += __shfl_xor_sync(0xffffffffu, ss1, o);
                }
                const float r0 = rsqrtf(ss0), r1 = rsqrtf(ss1);
                u0.x *= r0; u0.y *= r0;
                u1.x *= r1; u1.y *= r1;
            }
            const size_t base0 = ((((size_t)b * HH + h0) * SZ + s) << 6) + lane * 2;
            const size_t base1 = ((((size_t)b * HH + h0 + 1) * SZ + s) << 6) + lane * 2;
            *(__half2*)(dbuf + base0) = __floats2half2_rn(u0.x, u0.y);
            *(__half2*)(dbuf + base1) = __floats2half2_rn(u1.x, u1.y);
        }
    }
}

// ---------------------------------------------------------------------------
// kv partials: kvp[part][bh] = sum_{s in part} k^T v over 1024 seq positions.
// grid (4, 192); deterministic. Vectorized __half2 loads over d-pairs (full
// 128B/warp coalescing); store-side swizzle conflict-free for d and d+1 rows.
// tf32 fragment code identical to the proven R16 version.
// ---------------------------------------------------------------------------
__global__ __launch_bounds__(256) void kv_mma()
{
    __shared__ float ks[64 * 32];
    __shared__ float vs[64 * 32];

    const int part = blockIdx.x;
    const int bh = blockIdx.y;
    const __half* Kb = g_k + (size_t)bh * SZ * HD;
    const __half* Vb = g_v + (size_t)bh * SZ * HD;

    const int tid = threadIdx.x;
    const int wid = tid >> 5, lane = tid & 31;
    const int l4 = lane >> 2, lk = lane & 3;
    const int wm = wid & 1, wn = wid >> 1;

    // loader mapping: d-pair per thread
    const int dp = (tid & 31) * 2;        // d = dp, dp+1
    const int sg = tid >> 5;              // 0..7
    const int swz0 = ((dp & 7) << 2) + (dp >> 3);
    const int swz1 = (((dp + 1) & 7) << 2) + ((dp + 1) >> 3);

    const int d0 = wm * 32 + l4;
    const int e0 = wn * 16 + l4;

    float acc[2][2][4];
#pragma unroll
    for (int mi = 0; mi < 2; mi++)
#pragma unroll
        for (int ni = 0; ni < 2; ni++)
#pragma unroll
            for (int r = 0; r < 4; r++) acc[mi][ni][r] = 0.f;

    const int s_lo = part * 1024;
    for (int s0 = s_lo; s0 < s_lo + 1024; s0 += 32) {
        float2 kr[4], vr[4];
#pragma unroll
        for (int i = 0; i < 4; i++) {
            const int s = s0 + sg + i * 8;
            kr[i] = __half22float2(*(const __half2*)&Kb[(size_t)s * 64 + dp]);
            vr[i] = __half22float2(*(const __half2*)&Vb[(size_t)s * 64 + dp]);
        }
        __syncthreads();
#pragma unroll
        for (int i = 0; i < 4; i++) {
            const int sl = sg + i * 8;
            const int c0 = (sl + swz0) & 31;
            const int c1 = (sl + swz1) & 31;
            ks[dp * 32 + c0]       = kr[i].x;
            ks[(dp + 1) * 32 + c1] = kr[i].y;
            vs[dp * 32 + c0]       = vr[i].x;
            vs[(dp + 1) * 32 + c1] = vr[i].y;
        }
        __syncthreads();

#pragma unroll
        for (int kk = 0; kk < 4; kk++) {
            const int c0 = kk * 8 + lk;
            uint32_t af[2][4], bf[2][2];
#pragma unroll
            for (int mi = 0; mi < 2; mi++) {
                const int da = d0 + mi * 16;
                const int db = da + 8;
                const int swa = ((da & 7) << 2) + (da >> 3);
                const int swb = swa + 1;
                af[mi][0] = __float_as_uint(ks[da * 32 + ((c0 + swa) & 31)]);
                af[mi][1] = __float_as_uint(ks[db * 32 + ((c0 + swb) & 31)]);
                af[mi][2] = __float_as_uint(ks[da * 32 + ((c0 + 4 + swa) & 31)]);
                af[mi][3] = __float_as_uint(ks[db * 32 + ((c0 + 4 + swb) & 31)]);
            }
#pragma unroll
            for (int ni = 0; ni < 2; ni++) {
                const int ea = e0 + ni * 8;
                const int swe = ((ea & 7) << 2) + (ea >> 3);
                bf[ni][0] = __float_as_uint(vs[ea * 32 + ((c0 + swe) & 31)]);
                bf[ni][1] = __float_as_uint(vs[ea * 32 + ((c0 + 4 + swe) & 31)]);
            }
#pragma unroll
            for (int mi = 0; mi < 2; mi++)
#pragma unroll
                for (int ni = 0; ni < 2; ni++)
                    mma_tf32(acc[mi][ni], af[mi][0], af[mi][1], af[mi][2],
                             af[mi][3], bf[ni][0], bf[ni][1]);
        }
    }

    float* out = g_kvp + ((size_t)part * BZ * HH + bh) * HD * HD;
#pragma unroll
    for (int mi = 0; mi < 2; mi++)
#pragma unroll
        for (int ni = 0; ni < 2; ni++) {
            const int d = wm * 32 + mi * 16 + l4;
            const int e = wn * 16 + ni * 8 + lk * 2;
            *(float2*)&out[d * 64 + e]       = make_float2(acc[mi][ni][0], acc[mi][ni][1]);
            *(float2*)&out[(d + 8) * 64 + e] = make_float2(acc[mi][ni][2], acc[mi][ni][3]);
        }
}

// Sum the 4 kv partials into fp16 g_kvh.
__global__ void kv_reduce()
{
    const size_t i = ((size_t)blockIdx.x * blockDim.x + threadIdx.x) * 4;
    const size_t stride = (size_t)BZ * HH * HD * HD;
    float4 a = *(const float4*)&g_kvp[i];
    float4 b = *(const float4*)&g_kvp[i + stride];
    float4 c = *(const float4*)&g_kvp[i + 2 * stride];
    float4 d = *(const float4*)&g_kvp[i + 3 * stride];
    a.x += b.x + c.x + d.x;  a.y += b.y + c.y + d.y;
    a.z += b.z + c.z + d.z;  a.w += b.w + c.w + d.w;
    __half2 h01 = __floats2half2_rn(a.x, a.y);
    __half2 h23 = __floats2half2_rn(a.z, a.w);
    uint2 o;
    o.x = *(uint32_t*)&h01;
    o.y = *(uint32_t*)&h23;
    *(uint2*)&g_kvh[i] = o;
}

// ---------------------------------------------------------------------------
// out = normalize(0.5*v + (1/pi) q@kv) + dconv(v); q@kv via tf32 mma.sync.
// q,v,kv all read fp16 (exact in tf32). smem: kvT[64][68] | qs[64][68]
// (aliased ob) | vext[72][64]; g_y stored fp16.
// ---------------------------------------------------------------------------
#define OS_KVT 0
#define OS_QS  (64*68)
#define OS_VX  (2*64*68)
#define OS_WD  (2*64*68 + 72*64)
#define OUT_SMEM_FLOATS (2*64*68 + 72*64 + 16)
#define OUT_SMEM_BYTES  (OUT_SMEM_FLOATS * 4)

__global__ __launch_bounds__(256) void out_kernel(const float* __restrict__ wd)
{
    extern __shared__ float sm[];
    float* kvT  = sm + OS_KVT;
    float* qs   = sm + OS_QS;
    float* ob   = qs;
    float (*vext)[64] = (float(*)[64])(sm + OS_VX);
    float* wds  = sm + OS_WD;

    const int bh = blockIdx.y;
    const int bb = bh / HH;
    const int h  = bh % HH;
    const int s0 = blockIdx.x * 64;

    const __half* Qb = g_q + (size_t)bh * SZ * HD;
    const __half* Vb = g_v + (size_t)bh * SZ * HD;
    const __half* KVb = g_kvh + (size_t)bh * HD * HD;

    const int tid = threadIdx.x;
    const int wid = tid >> 5, lane = tid & 31;
    const int l4 = lane >> 2, lk = lane & 3;
    const int wm = wid & 1, wn = wid >> 1;

    // kv (fp16, tf32-exact) -> kvT transposed
#pragma unroll
    for (int i = tid * 4; i < 4096; i += 1024) {
        const int d = i >> 6, e = i & 63;
        uint2 u = *(const uint2*)(KVb + i);
        float2 f0 = __half22float2(*(__half2*)&u.x);
        float2 f1 = __half22float2(*(__half2*)&u.y);
        kvT[(e + 0) * 68 + d] = f0.x;
        kvT[(e + 1) * 68 + d] = f0.y;
        kvT[(e + 2) * 68 + d] = f1.x;
        kvT[(e + 3) * 68 + d] = f1.y;
    }

    // q (fp16, tf32-exact) -> qs
#pragma unroll
    for (int i = tid * 4; i < 4096; i += 1024) {
        const int r = i >> 6, c = i & 63;
        uint2 u = *(const uint2*)(Qb + (size_t)(s0 + r) * 64 + c);
        float2 f0 = __half22float2(*(__half2*)&u.x);
        float2 f1 = __half22float2(*(__half2*)&u.y);
        *(float4*)(qs + r * 68 + c) = make_float4(f0.x, f0.y, f1.x, f1.y);
    }

    // v (fp16) with +-4 halo
    for (int i = tid * 4; i < 72 * 64; i += 1024) {
        const int r = i >> 6, c = i & 63;
        const int gs = s0 - 4 + r;
        float4 val = make_float4(0.f, 0.f, 0.f, 0.f);
        if (gs >= 0 && gs < SZ) {
            uint2 u = *(const uint2*)(Vb + (size_t)gs * 64 + c);
            float2 f0 = __half22float2(*(__half2*)&u.x);
            float2 f1 = __half22float2(*(__half2*)&u.y);
            val = make_float4(f0.x, f0.y, f1.x, f1.y);
        }
        *(float4*)&vext[r][c] = val;
    }
    if (tid < KSZ) wds[tid] = wd[h * KSZ + tid];
    __syncthreads();

    float acc[2][2][4];
#pragma unroll
    for (int mi = 0; mi < 2; mi++)
#pragma unroll
        for (int ni = 0; ni < 2; ni++)
#pragma unroll
            for (int r = 0; r < 4; r++) acc[mi][ni][r] = 0.f;

#pragma unroll
    for (int kk = 0; kk < 8; kk++) {
        const int d = kk * 8 + lk;
        uint32_t af[2][4], bf[2][2];
#pragma unroll
        for (int mi = 0; mi < 2; mi++) {
            const int m0 = wm * 32 + mi * 16 + l4;
            af[mi][0] = __float_as_uint(qs[m0 * 68 + d]);
            af[mi][1] = __float_as_uint(qs[(m0 + 8) * 68 + d]);
            af[mi][2] = __float_as_uint(qs[m0 * 68 + d + 4]);
            af[mi][3] = __float_as_uint(qs[(m0 + 8) * 68 + d + 4]);
        }
#pragma unroll
        for (int ni = 0; ni < 2; ni++) {
            const int n0 = wn * 16 + ni * 8 + l4;
            bf[ni][0] = __float_as_uint(kvT[n0 * 68 + d]);
            bf[ni][1] = __float_as_uint(kvT[n0 * 68 + d + 4]);
        }
#pragma unroll
        for (int mi = 0; mi < 2; mi++)
#pragma unroll
            for (int ni = 0; ni < 2; ni++)
                mma_tf32(acc[mi][ni], af[mi][0], af[mi][1], af[mi][2],
                         af[mi][3], bf[ni][0], bf[ni][1]);
    }
    __syncthreads();

#pragma unroll
    for (int mi = 0; mi < 2; mi++)
#pragma unroll
        for (int ni = 0; ni < 2; ni++) {
            const int r = wm * 32 + mi * 16 + l4;
            const int cc = wn * 16 + ni * 8 + lk * 2;
            ob[r * 68 + cc]           = acc[mi][ni][0];
            ob[r * 68 + cc + 1]       = acc[mi][ni][1];
            ob[(r + 8) * 68 + cc]     = acc[mi][ni][2];
            ob[(r + 8) * 68 + cc + 1] = acc[mi][ni][3];
        }
    __syncthreads();

    const float INV_PI = 0.3183098861837907f;
#pragma unroll
    for (int k = 0; k < 8; k++) {
        const int rr = wid * 8 + k;
        const float v0 = 0.5f * vext[rr + 4][lane]      + INV_PI * ob[rr * 68 + lane];
        const float v1 = 0.5f * vext[rr + 4][lane + 32] + INV_PI * ob[rr * 68 + lane + 32];
        float ss = v0 * v0 + v1 * v1;
#pragma unroll
        for (int o = 16; o; o >>= 1) ss += __shfl_xor_sync(0xffffffffu, ss, o);
        const float rn = rsqrtf(ss);
        float c0 = 0.f, c1 = 0.f;
#pragma unroll
        for (int j = 0; j < KSZ; j++) {
            const float w = wds[j];
            c0 += vext[rr + j][lane] * w;
            c1 += vext[rr + j][lane + 32] * w;
        }
        const int sg = s0 + rr;
        __half* dst = g_y + ((size_t)bb * SZ + sg) * DZ + h * HD;
        dst[lane]      = __float2half_rn(v0 * rn + c0);
        dst[lane + 32] = __float2half_rn(v1 * rn + c1);
    }
}

// ---------------------------------------------------------------------------
extern "C" void kernel_launch(void* const* d_in, const int* in_sizes, int n_in,
                              void* d_out, int out_size)
{
    const float* x      = (const float*)d_in[0];
    const float* w_qkv  = (const float*)d_in[1];
    const float* b_qkv  = (const float*)d_in[2];
    const float* w_proj = (const float*)d_in[3];
    const float* b_proj = (const float*)d_in[4];
    const float* w_dcv  = (const float*)d_in[5];
    float* out = (float*)d_out;

    cudaFuncSetAttribute(gemm_mma<1, KDIM/BKT>, cudaFuncAttributeMaxDynamicSharedMemorySize, GEMM_SMEM);
    cudaFuncSetAttribute(gemm_mma<0, KDIM/BKT>, cudaFuncAttributeMaxDynamicSharedMemorySize, GEMM_SMEM);
    cudaFuncSetAttribute(out_kernel, cudaFuncAttributeMaxDynamicSharedMemorySize, OUT_SMEM_BYTES);

    // fp16-convert all GEMM inputs in one launch (RN, unbiased)
    const int n4_total = N4_X + N4_WQ + N4_WP;
    cvt_all<<<(n4_total + 255) / 256, 256>>>((const float4*)x,
                                             (const float4*)w_qkv,
                                             (const float4*)w_proj);

    // QKV projection (fp16 mma) + fused bias + q/k normalize + fp16 scatter
    gemm_mma<1, KDIM/BKT><<<dim3(3 * DZ / BNT, MTOT / BMT), 256, GEMM_SMEM>>>(b_qkv, nullptr);
    // kv = k^T v: 4 deterministic S-partials + fp16 reduce
    kv_mma<<<dim3(4, BZ * HH), 256>>>();
    kv_reduce<<<(BZ * HH * HD * HD) / 1024, 256>>>();
    // angular attention core (tf32) + norm + dconv + relayout -> fp16 g_y
    out_kernel<<<dim3(SZ / 64, BZ * HH), 256, OUT_SMEM_BYTES>>>(w_dcv);
    // output projection (fp16 mma)
    gemm_mma<0, KDIM/BKT><<<dim3(DZ / BNT, MTOT / BMT), 256, GEMM_SMEM>>>(b_proj, out);
}